// round 11
// baseline (speedup 1.0000x reference)
#include <cuda_runtime.h>
#include <stdint.h>
#include <math.h>

#define NT 256

static const int TILES = 64;   // N*W = 4*16
static const int P     = 128;
static const int DD    = 96;
static const int SELK  = 100;
static const int GCHN  = 101;
static const int LCHN  = 80;
static const int SPLIT = 4;
static const int RPC   = 32;   // rows per CTA (4 per warp)
static const int VRS   = 100;  // V row stride (floats): mult of 4, 25 float4s (odd) -> LDS.128 conflict-free

__device__ __align__(16) float g_Mt[DD*DD];   // g_Mt[j][b] = (W_q^T W_k)[b][j]
__device__ __align__(16) float g_c[DD];       // W_k^T b_q
__device__ float g_scale[GCHN];               // sigmoid(mb @ w_up^T + b_up)

__global__ void setup_kernel(const float* __restrict__ mb,
                             const float* __restrict__ w_up,
                             const float* __restrict__ b_up,
                             const float* __restrict__ w_q,
                             const float* __restrict__ b_q,
                             const float* __restrict__ w_k)
{
    int blk = blockIdx.x;   // j index
    int t   = threadIdx.x;  // b index
    if (blk < DD) {
        if (t < DD) {
            float acc = 0.f;
            #pragma unroll 8
            for (int k = 0; k < DD; k++)
                acc += w_q[k*DD + t] * w_k[k*DD + blk];
            g_Mt[blk*DD + t] = acc;    // g_Mt[j=blk][b=t] = sum_k w_q[k,b] w_k[k,j]
        }
    } else {
        if (t < DD) {
            float acc = 0.f;
            #pragma unroll 8
            for (int k = 0; k < DD; k++)
                acc += b_q[k] * w_k[k*DD + t];
            g_c[t] = acc;
        }
        if (t < GCHN) {
            float acc = b_up[t];
            #pragma unroll 8
            for (int l = 0; l < LCHN; l++)
                acc += w_up[t*LCHN + l] * mb[l];
            g_scale[t] = 1.f / (1.f + __expf(-acc));
        }
    }
}

__global__ __launch_bounds__(NT, 2) void fused_kernel(
    const float* __restrict__ attn,
    const float* __restrict__ v,
    const float* __restrict__ w_o,
    const float* __restrict__ b_o,
    float* __restrict__ out)
{
    extern __shared__ float sm[];
    float* Vr  = sm;              // [P][VRS]  V row-major (как input), float4-aligned rows
    float* As  = Vr + P*VRS;      // [RPC][DD] A = V_rows @ M ; later reused as Os
    float* cvs = As + RPC*DD;     // [P]       c . V_i
    float* ssc = cvs + P;         // [104]     scale table

    const int tile = blockIdx.x / SPLIT;
    const int part = blockIdx.x % SPLIT;
    const int tid  = threadIdx.x;
    const int w    = tid >> 5;
    const int lane = tid & 31;
    const int row_base = part * RPC;
    const unsigned FULL = 0xffffffffu;

    // --- load V tile row-major, float4 end to end ---
    const float4* vt4 = (const float4*)(v + (size_t)tile * P * DD);
    #pragma unroll
    for (int k = 0; k < (P*DD/4)/NT; k++) {     // 12 iterations
        int f = tid + k*NT;                      // float4 index
        int i = f / 24;                          // 24 float4 per source row
        int d4 = f - i*24;
        *(float4*)(Vr + i*VRS + d4*4) = vt4[f];
    }
    if (tid < GCHN) ssc[tid] = g_scale[tid];
    __syncthreads();

    // --- cvs[i] = sum_b c[b] * V[i][b] (vectorized) ---
    if (tid < P) {
        const float4* vp = (const float4*)(Vr + tid*VRS);
        const float4* cp = (const float4*)g_c;
        float acc = 0.f;
        #pragma unroll 6
        for (int b4 = 0; b4 < DD/4; b4++) {
            float4 vv = vp[b4];
            float4 cc = cp[b4];
            acc += vv.x*cc.x + vv.y*cc.y + vv.z*cc.z + vv.w*cc.w;
        }
        cvs[tid] = acc;
    }
    __syncthreads();

    // --- attn rows straight to registers as ordered uints (early LDG) ---
    const float* at = attn + (size_t)tile * P * P;
    uint32_t u[4][4];
    #pragma unroll
    for (int rr = 0; rr < 4; rr++) {
        const float* arow = at + (size_t)(row_base + 4*w + rr) * P;
        #pragma unroll
        for (int c = 0; c < 4; c++) {
            uint32_t s = __float_as_uint(arow[lane + 32*c]);
            u[rr][c] = s ^ ((uint32_t)((int32_t)s >> 31) | 0x80000000u);
        }
    }

    // --- Phase A: As[r][j] = sum_b V[row][b] * M[b][j], vectorized over b ---
    {
        float a0[4], a1[4], a2[4];
        #pragma unroll
        for (int rr = 0; rr < 4; rr++) { a0[rr]=0.f; a1[rr]=0.f; a2[rr]=0.f; }
        const float4* vp0 = (const float4*)(Vr + (row_base + 4*w + 0)*VRS);
        const float4* vp1 = (const float4*)(Vr + (row_base + 4*w + 1)*VRS);
        const float4* vp2 = (const float4*)(Vr + (row_base + 4*w + 2)*VRS);
        const float4* vp3 = (const float4*)(Vr + (row_base + 4*w + 3)*VRS);
        const float4* mt0 = (const float4*)(g_Mt + (lane     )*DD);
        const float4* mt1 = (const float4*)(g_Mt + (lane + 32)*DD);
        const float4* mt2 = (const float4*)(g_Mt + (lane + 64)*DD);
        #pragma unroll 4
        for (int b4 = 0; b4 < DD/4; b4++) {
            float4 m0 = mt0[b4], m1 = mt1[b4], m2 = mt2[b4];
            float4 vv0 = vp0[b4], vv1 = vp1[b4], vv2 = vp2[b4], vv3 = vp3[b4];
            a0[0] += vv0.x*m0.x + vv0.y*m0.y + vv0.z*m0.z + vv0.w*m0.w;
            a1[0] += vv0.x*m1.x + vv0.y*m1.y + vv0.z*m1.z + vv0.w*m1.w;
            a2[0] += vv0.x*m2.x + vv0.y*m2.y + vv0.z*m2.z + vv0.w*m2.w;
            a0[1] += vv1.x*m0.x + vv1.y*m0.y + vv1.z*m0.z + vv1.w*m0.w;
            a1[1] += vv1.x*m1.x + vv1.y*m1.y + vv1.z*m1.z + vv1.w*m1.w;
            a2[1] += vv1.x*m2.x + vv1.y*m2.y + vv1.z*m2.z + vv1.w*m2.w;
            a0[2] += vv2.x*m0.x + vv2.y*m0.y + vv2.z*m0.z + vv2.w*m0.w;
            a1[2] += vv2.x*m1.x + vv2.y*m1.y + vv2.z*m1.z + vv2.w*m1.w;
            a2[2] += vv2.x*m2.x + vv2.y*m2.y + vv2.z*m2.z + vv2.w*m2.w;
            a0[3] += vv3.x*m0.x + vv3.y*m0.y + vv3.z*m0.z + vv3.w*m0.w;
            a1[3] += vv3.x*m1.x + vv3.y*m1.y + vv3.z*m1.z + vv3.w*m1.w;
            a2[3] += vv3.x*m2.x + vv3.y*m2.y + vv3.z*m2.z + vv3.w*m2.w;
        }
        #pragma unroll
        for (int rr = 0; rr < 4; rr++) {
            As[(4*w+rr)*DD + lane]      = a0[rr];
            As[(4*w+rr)*DD + lane + 32] = a1[rr];
            As[(4*w+rr)*DD + lane + 64] = a2[rr];
        }
    }
    __syncwarp();

    // --- Top-100 per row via radix bisection on ordered-uint prefixes ---
    uint32_t pre[4] = {0u, 0u, 0u, 0u};
    #pragma unroll 1
    for (int bb = 31; bb >= 0; bb--) {
        uint32_t bit = 1u << bb;
        #pragma unroll
        for (int rr = 0; rr < 4; rr++) {
            uint32_t cand = pre[rr] | bit;
            int lc = (int)(u[rr][0] >= cand) + (int)(u[rr][1] >= cand)
                   + (int)(u[rr][2] >= cand) + (int)(u[rr][3] >= cand);
            int tot = __reduce_add_sync(FULL, lc);
            if (tot >= SELK) pre[rr] = cand;
        }
    }

    // --- selected mask + ascending-index rank -> scale value (registers) ---
    float sval[4][4];
    #pragma unroll
    for (int rr = 0; rr < 4; rr++) {
        bool s0 = u[rr][0] >= pre[rr];
        bool s1 = u[rr][1] >= pre[rr];
        bool s2 = u[rr][2] >= pre[rr];
        bool s3 = u[rr][3] >= pre[rr];
        unsigned m0 = __ballot_sync(FULL, s0);
        unsigned m1 = __ballot_sync(FULL, s1);
        unsigned m2 = __ballot_sync(FULL, s2);
        unsigned m3 = __ballot_sync(FULL, s3);
        unsigned lm = (1u << lane) - 1u;
        int t0 = __popc(m0), t1 = __popc(m1), t2 = __popc(m2);
        int r0 = 1 + __popc(m0 & lm);
        int r1 = 1 + t0 + __popc(m1 & lm);
        int r2 = 1 + t0 + t1 + __popc(m2 & lm);
        int r3 = 1 + t0 + t1 + t2 + __popc(m3 & lm);
        sval[rr][0] = s0 ? ssc[min(r0, SELK)] : 0.f;
        sval[rr][1] = s1 ? ssc[min(r1, SELK)] : 0.f;
        sval[rr][2] = s2 ? ssc[min(r2, SELK)] : 0.f;
        sval[rr][3] = s3 ? ssc[min(r3, SELK)] : 0.f;
    }

    // --- S = A . V^T (vectorized over b), masked softmax -> weights ---
    const float s0c   = ssc[0];
    const float inv96 = 0.1020620726159657f;  // 1/sqrt(96)
    {
        float dot[4][4];
        #pragma unroll
        for (int rr = 0; rr < 4; rr++)
            #pragma unroll
            for (int c = 0; c < 4; c++) dot[rr][c] = 0.f;

        const float4* vp0 = (const float4*)(Vr + (lane     )*VRS);
        const float4* vp1 = (const float4*)(Vr + (lane + 32)*VRS);
        const float4* vp2 = (const float4*)(Vr + (lane + 64)*VRS);
        const float4* vp3 = (const float4*)(Vr + (lane + 96)*VRS);
        const float4* ap0 = (const float4*)(As + (4*w + 0)*DD);
        const float4* ap1 = (const float4*)(As + (4*w + 1)*DD);
        const float4* ap2 = (const float4*)(As + (4*w + 2)*DD);
        const float4* ap3 = (const float4*)(As + (4*w + 3)*DD);
        #pragma unroll 2
        for (int b4 = 0; b4 < DD/4; b4++) {
            float4 v0 = vp0[b4], v1 = vp1[b4], v2 = vp2[b4], v3 = vp3[b4];
            float4 av0 = ap0[b4], av1 = ap1[b4], av2 = ap2[b4], av3 = ap3[b4];
            dot[0][0] += av0.x*v0.x + av0.y*v0.y + av0.z*v0.z + av0.w*v0.w;
            dot[0][1] += av0.x*v1.x + av0.y*v1.y + av0.z*v1.z + av0.w*v1.w;
            dot[0][2] += av0.x*v2.x + av0.y*v2.y + av0.z*v2.z + av0.w*v2.w;
            dot[0][3] += av0.x*v3.x + av0.y*v3.y + av0.z*v3.z + av0.w*v3.w;
            dot[1][0] += av1.x*v0.x + av1.y*v0.y + av1.z*v0.z + av1.w*v0.w;
            dot[1][1] += av1.x*v1.x + av1.y*v1.y + av1.z*v1.z + av1.w*v1.w;
            dot[1][2] += av1.x*v2.x + av1.y*v2.y + av1.z*v2.z + av1.w*v2.w;
            dot[1][3] += av1.x*v3.x + av1.y*v3.y + av1.z*v3.z + av1.w*v3.w;
            dot[2][0] += av2.x*v0.x + av2.y*v0.y + av2.z*v0.z + av2.w*v0.w;
            dot[2][1] += av2.x*v1.x + av2.y*v1.y + av2.z*v1.z + av2.w*v1.w;
            dot[2][2] += av2.x*v2.x + av2.y*v2.y + av2.z*v2.z + av2.w*v2.w;
            dot[2][3] += av2.x*v3.x + av2.y*v3.y + av2.z*v3.z + av2.w*v3.w;
            dot[3][0] += av3.x*v0.x + av3.y*v0.y + av3.z*v0.z + av3.w*v0.w;
            dot[3][1] += av3.x*v1.x + av3.y*v1.y + av3.z*v1.z + av3.w*v1.w;
            dot[3][2] += av3.x*v2.x + av3.y*v2.y + av3.z*v2.z + av3.w*v2.w;
            dot[3][3] += av3.x*v3.x + av3.y*v3.y + av3.z*v3.z + av3.w*v3.w;
        }

        float cv[4];
        #pragma unroll
        for (int c = 0; c < 4; c++) cv[c] = cvs[lane + 32*c];

        #pragma unroll
        for (int rr = 0; rr < 4; rr++) {
            float sc[4];
            float mx = -1e30f;
            #pragma unroll
            for (int c = 0; c < 4; c++) {
                float s = sval[rr][c] * (s0c * dot[rr][c] + cv[c]) * inv96;
                sc[c] = (sval[rr][c] != 0.f) ? s : -1e30f;
                mx = fmaxf(mx, sc[c]);
            }
            #pragma unroll
            for (int o = 16; o > 0; o >>= 1)
                mx = fmaxf(mx, __shfl_xor_sync(FULL, mx, o));
            float e[4], sum = 0.f;
            #pragma unroll
            for (int c = 0; c < 4; c++) { e[c] = __expf(sc[c] - mx); sum += e[c]; }
            #pragma unroll
            for (int o = 16; o > 0; o >>= 1)
                sum += __shfl_xor_sync(FULL, sum, o);
            float rs = 1.0f / sum;
            #pragma unroll
            for (int c = 0; c < 4; c++)
                sval[rr][c] = sval[rr][c] * e[c] * rs;   // final combined weight
        }
    }

    // --- Os = Wfull (32x128) @ V (128x96); weights broadcast via shfl ---
    float o0[4], o1[4], o2[4];
    #pragma unroll
    for (int rr = 0; rr < 4; rr++) { o0[rr]=0.f; o1[rr]=0.f; o2[rr]=0.f; }
    {
        const float* vb0 = Vr + lane;
        const float* vb1 = Vr + lane + 32;
        const float* vb2 = Vr + lane + 64;
        #pragma unroll 1
        for (int c4 = 0; c4 < 4; c4++) {
            #pragma unroll 4
            for (int l = 0; l < 32; l++) {
                int i = c4*32 + l;
                float v0 = vb0[i*VRS];
                float v1 = vb1[i*VRS];
                float v2 = vb2[i*VRS];
                #pragma unroll
                for (int rr = 0; rr < 4; rr++) {
                    float wv = __shfl_sync(FULL, sval[rr][c4], l);
                    o0[rr] += wv*v0; o1[rr] += wv*v1; o2[rr] += wv*v2;
                }
            }
        }
    }
    __syncwarp();   // all lanes finished reading As (dot phase) before overwrite
    #pragma unroll
    for (int rr = 0; rr < 4; rr++) {
        As[(4*w+rr)*DD + lane]      = o0[rr];
        As[(4*w+rr)*DD + lane + 32] = o1[rr];
        As[(4*w+rr)*DD + lane + 64] = o2[rr];
    }
    __syncwarp();

    // --- final = Os @ W_o^T + b_o (vectorized over t), write out ---
    {
        float f0[4], f1[4], f2[4];
        #pragma unroll
        for (int rr = 0; rr < 4; rr++) { f0[rr]=0.f; f1[rr]=0.f; f2[rr]=0.f; }
        const float4* os0 = (const float4*)(As + (4*w + 0)*DD);
        const float4* os1 = (const float4*)(As + (4*w + 1)*DD);
        const float4* os2 = (const float4*)(As + (4*w + 2)*DD);
        const float4* os3 = (const float4*)(As + (4*w + 3)*DD);
        const float4* wp0 = (const float4*)(w_o + (lane     )*DD);
        const float4* wp1 = (const float4*)(w_o + (lane + 32)*DD);
        const float4* wp2 = (const float4*)(w_o + (lane + 64)*DD);
        #pragma unroll 4
        for (int t4 = 0; t4 < DD/4; t4++) {
            float4 w0 = wp0[t4], w1 = wp1[t4], w2 = wp2[t4];
            float4 q0 = os0[t4], q1 = os1[t4], q2 = os2[t4], q3 = os3[t4];
            f0[0] += q0.x*w0.x + q0.y*w0.y + q0.z*w0.z + q0.w*w0.w;
            f1[0] += q0.x*w1.x + q0.y*w1.y + q0.z*w1.z + q0.w*w1.w;
            f2[0] += q0.x*w2.x + q0.y*w2.y + q0.z*w2.z + q0.w*w2.w;
            f0[1] += q1.x*w0.x + q1.y*w0.y + q1.z*w0.z + q1.w*w0.w;
            f1[1] += q1.x*w1.x + q1.y*w1.y + q1.z*w1.z + q1.w*w1.w;
            f2[1] += q1.x*w2.x + q1.y*w2.y + q1.z*w2.z + q1.w*w2.w;
            f0[2] += q2.x*w0.x + q2.y*w0.y + q2.z*w0.z + q2.w*w0.w;
            f1[2] += q2.x*w1.x + q2.y*w1.y + q2.z*w1.z + q2.w*w1.w;
            f2[2] += q2.x*w2.x + q2.y*w2.y + q2.z*w2.z + q2.w*w2.w;
            f0[3] += q3.x*w0.x + q3.y*w0.y + q3.z*w0.z + q3.w*w0.w;
            f1[3] += q3.x*w1.x + q3.y*w1.y + q3.z*w1.z + q3.w*w1.w;
            f2[3] += q3.x*w2.x + q3.y*w2.y + q3.z*w2.z + q3.w*w2.w;
        }
        float bb0 = b_o[lane], bb1 = b_o[lane+32], bb2 = b_o[lane+64];
        #pragma unroll
        for (int rr = 0; rr < 4; rr++) {
            int arow = row_base + 4*w + rr;
            float* op = out + (size_t)tile*P*DD + (size_t)arow*DD;
            op[lane]      = f0[rr] + bb0;
            op[lane + 32] = f1[rr] + bb1;
            op[lane + 64] = f2[rr] + bb2;
        }
    }
}

extern "C" void kernel_launch(void* const* d_in, const int* in_sizes, int n_in,
                              void* d_out, int out_size)
{
    const float* attn = (const float*)d_in[0];
    const float* v    = (const float*)d_in[1];
    const float* mb   = (const float*)d_in[2];
    // d_in[3]=w_sub, d_in[4]=b_sub : dead code (softmax over size-1 axis)
    const float* w_up = (const float*)d_in[5];
    const float* b_up = (const float*)d_in[6];
    const float* w_q  = (const float*)d_in[7];
    const float* b_q  = (const float*)d_in[8];
    const float* w_k  = (const float*)d_in[9];
    // d_in[10]=b_k : row-constant in scores, cancels in softmax
    const float* w_o  = (const float*)d_in[11];
    const float* b_o  = (const float*)d_in[12];

    const size_t SMEM = (size_t)(P*VRS + RPC*DD + P + 104) * sizeof(float);
    cudaFuncSetAttribute(fused_kernel, cudaFuncAttributeMaxDynamicSharedMemorySize, (int)SMEM);

    setup_kernel<<<DD + 1, 128>>>(mb, w_up, b_up, w_q, b_q, w_k);
    fused_kernel<<<TILES * SPLIT, NT, SMEM>>>(attn, v, w_o, b_o, (float*)d_out);
}

// round 13
// speedup vs baseline: 1.5053x; 1.5053x over previous
#include <cuda_runtime.h>
#include <stdint.h>
#include <math.h>

#define NT 256

static const int TILES = 64;   // N*W = 4*16
static const int P     = 128;
static const int DD    = 96;
static const int SELK  = 100;
static const int GCHN  = 101;
static const int LCHN  = 80;
static const int SPLIT = 4;
static const int RPC   = 32;   // rows per CTA (4 per warp)
static const int VRS   = 100;  // V row stride (floats)

// k-block-major packed weights: coalesced float4 loads (lane-consecutive)
__device__ __align__(16) float4 g_Mp[(DD/4)*DD];  // [b4][j] = M[4b4..4b4+3][j]
__device__ __align__(16) float4 g_Wp[(DD/4)*DD];  // [t4][d] = w_o[d][4t4..4t4+3]
__device__ __align__(16) float g_c[DD];           // W_k^T b_q
__device__ float g_scale[GCHN];                   // sigmoid(mb @ w_up^T + b_up)

__global__ void setup_kernel(const float* __restrict__ mb,
                             const float* __restrict__ w_up,
                             const float* __restrict__ b_up,
                             const float* __restrict__ w_q,
                             const float* __restrict__ b_q,
                             const float* __restrict__ w_k,
                             const float* __restrict__ w_o)
{
    int blk = blockIdx.x;
    int t   = threadIdx.x;
    if (blk < DD/4) {
        // g_Mp[blk][j=t]: M[b][j] = sum_k w_q[k][b] * w_k[k][j]
        if (t < DD) {
            float a0=0.f, a1=0.f, a2=0.f, a3=0.f;
            int b = blk*4;
            #pragma unroll 8
            for (int k = 0; k < DD; k++) {
                float wk = w_k[k*DD + t];
                a0 += w_q[k*DD + b+0] * wk;
                a1 += w_q[k*DD + b+1] * wk;
                a2 += w_q[k*DD + b+2] * wk;
                a3 += w_q[k*DD + b+3] * wk;
            }
            g_Mp[blk*DD + t] = make_float4(a0, a1, a2, a3);
        }
    } else if (blk < DD/2) {
        // g_Wp[t4][d] = w_o[d][4t4..4t4+3]
        int t4 = blk - DD/4;
        if (t < DD) {
            const float* wr = w_o + t*DD + t4*4;
            g_Wp[t4*DD + t] = make_float4(wr[0], wr[1], wr[2], wr[3]);
        }
    } else {
        if (t < DD) {
            float acc = 0.f;
            #pragma unroll 8
            for (int k = 0; k < DD; k++)
                acc += b_q[k] * w_k[k*DD + t];
            g_c[t] = acc;
        }
        if (t < GCHN) {
            float acc = b_up[t];
            #pragma unroll 8
            for (int l = 0; l < LCHN; l++)
                acc += w_up[t*LCHN + l] * mb[l];
            g_scale[t] = 1.f / (1.f + __expf(-acc));
        }
    }
}

__global__ __launch_bounds__(NT, 2) void fused_kernel(
    const float* __restrict__ attn,
    const float* __restrict__ v,
    const float* __restrict__ b_o,
    float* __restrict__ out)
{
    extern __shared__ float sm[];
    float* Vr  = sm;              // [P][VRS]  V row-major, float4-aligned rows
    float* As  = Vr + P*VRS;      // [RPC][DD] A = V_rows @ M ; later reused as Os
    float* cvs = As + RPC*DD;     // [P]       c . V_i
    float* ssc = cvs + P;         // [104]     scale table

    const int tile = blockIdx.x / SPLIT;
    const int part = blockIdx.x % SPLIT;
    const int tid  = threadIdx.x;
    const int w    = tid >> 5;
    const int lane = tid & 31;
    const int row_base = part * RPC;
    const unsigned FULL = 0xffffffffu;

    // --- load V tile row-major, float4 end to end ---
    const float4* vt4 = (const float4*)(v + (size_t)tile * P * DD);
    #pragma unroll
    for (int k = 0; k < (P*DD/4)/NT; k++) {     // 12 iterations
        int f = tid + k*NT;                      // float4 index
        int i = f / 24;                          // 24 float4 per source row
        int d4 = f - i*24;
        *(float4*)(Vr + i*VRS + d4*4) = vt4[f];
    }
    if (tid < GCHN) ssc[tid] = g_scale[tid];
    __syncthreads();

    // --- cvs[i] = sum_b c[b] * V[i][b] (vectorized) ---
    if (tid < P) {
        const float4* vp = (const float4*)(Vr + tid*VRS);
        const float4* cp = (const float4*)g_c;
        float acc = 0.f;
        #pragma unroll 6
        for (int b4 = 0; b4 < DD/4; b4++) {
            float4 vv = vp[b4];
            float4 cc = cp[b4];
            acc += vv.x*cc.x + vv.y*cc.y + vv.z*cc.z + vv.w*cc.w;
        }
        cvs[tid] = acc;
    }
    __syncthreads();

    // --- attn rows straight to registers as ordered uints (early LDG) ---
    const float* at = attn + (size_t)tile * P * P;
    uint32_t u[4][4];
    #pragma unroll
    for (int rr = 0; rr < 4; rr++) {
        const float* arow = at + (size_t)(row_base + 4*w + rr) * P;
        #pragma unroll
        for (int c = 0; c < 4; c++) {
            uint32_t s = __float_as_uint(arow[lane + 32*c]);
            u[rr][c] = s ^ ((uint32_t)((int32_t)s >> 31) | 0x80000000u);
        }
    }

    // --- Phase A: As[r][j] = sum_b V[row][b] * M[b][j], coalesced packed M ---
    {
        float a0[4], a1[4], a2[4];
        #pragma unroll
        for (int rr = 0; rr < 4; rr++) { a0[rr]=0.f; a1[rr]=0.f; a2[rr]=0.f; }
        const float4* vp0 = (const float4*)(Vr + (row_base + 4*w + 0)*VRS);
        const float4* vp1 = (const float4*)(Vr + (row_base + 4*w + 1)*VRS);
        const float4* vp2 = (const float4*)(Vr + (row_base + 4*w + 2)*VRS);
        const float4* vp3 = (const float4*)(Vr + (row_base + 4*w + 3)*VRS);
        #pragma unroll 4
        for (int b4 = 0; b4 < DD/4; b4++) {
            float4 m0 = g_Mp[b4*DD + lane];
            float4 m1 = g_Mp[b4*DD + lane + 32];
            float4 m2 = g_Mp[b4*DD + lane + 64];
            float4 vv0 = vp0[b4], vv1 = vp1[b4], vv2 = vp2[b4], vv3 = vp3[b4];
            a0[0] += vv0.x*m0.x + vv0.y*m0.y + vv0.z*m0.z + vv0.w*m0.w;
            a1[0] += vv0.x*m1.x + vv0.y*m1.y + vv0.z*m1.z + vv0.w*m1.w;
            a2[0] += vv0.x*m2.x + vv0.y*m2.y + vv0.z*m2.z + vv0.w*m2.w;
            a0[1] += vv1.x*m0.x + vv1.y*m0.y + vv1.z*m0.z + vv1.w*m0.w;
            a1[1] += vv1.x*m1.x + vv1.y*m1.y + vv1.z*m1.z + vv1.w*m1.w;
            a2[1] += vv1.x*m2.x + vv1.y*m2.y + vv1.z*m2.z + vv1.w*m2.w;
            a0[2] += vv2.x*m0.x + vv2.y*m0.y + vv2.z*m0.z + vv2.w*m0.w;
            a1[2] += vv2.x*m1.x + vv2.y*m1.y + vv2.z*m1.z + vv2.w*m1.w;
            a2[2] += vv2.x*m2.x + vv2.y*m2.y + vv2.z*m2.z + vv2.w*m2.w;
            a0[3] += vv3.x*m0.x + vv3.y*m0.y + vv3.z*m0.z + vv3.w*m0.w;
            a1[3] += vv3.x*m1.x + vv3.y*m1.y + vv3.z*m1.z + vv3.w*m1.w;
            a2[3] += vv3.x*m2.x + vv3.y*m2.y + vv3.z*m2.z + vv3.w*m2.w;
        }
        #pragma unroll
        for (int rr = 0; rr < 4; rr++) {
            As[(4*w+rr)*DD + lane]      = a0[rr];
            As[(4*w+rr)*DD + lane + 32] = a1[rr];
            As[(4*w+rr)*DD + lane + 64] = a2[rr];
        }
    }
    __syncwarp();

    // --- Top-100 per row via radix bisection on ordered-uint prefixes ---
    uint32_t pre[4] = {0u, 0u, 0u, 0u};
    #pragma unroll 1
    for (int bb = 31; bb >= 0; bb--) {
        uint32_t bit = 1u << bb;
        #pragma unroll
        for (int rr = 0; rr < 4; rr++) {
            uint32_t cand = pre[rr] | bit;
            int lc = (int)(u[rr][0] >= cand) + (int)(u[rr][1] >= cand)
                   + (int)(u[rr][2] >= cand) + (int)(u[rr][3] >= cand);
            int tot = __reduce_add_sync(FULL, lc);
            if (tot >= SELK) pre[rr] = cand;
        }
    }

    // --- selected mask + ascending-index rank -> scale value (registers) ---
    float sval[4][4];
    #pragma unroll
    for (int rr = 0; rr < 4; rr++) {
        bool s0 = u[rr][0] >= pre[rr];
        bool s1 = u[rr][1] >= pre[rr];
        bool s2 = u[rr][2] >= pre[rr];
        bool s3 = u[rr][3] >= pre[rr];
        unsigned m0 = __ballot_sync(FULL, s0);
        unsigned m1 = __ballot_sync(FULL, s1);
        unsigned m2 = __ballot_sync(FULL, s2);
        unsigned m3 = __ballot_sync(FULL, s3);
        unsigned lm = (1u << lane) - 1u;
        int t0 = __popc(m0), t1 = __popc(m1), t2 = __popc(m2);
        int r0 = 1 + __popc(m0 & lm);
        int r1 = 1 + t0 + __popc(m1 & lm);
        int r2 = 1 + t0 + t1 + __popc(m2 & lm);
        int r3 = 1 + t0 + t1 + t2 + __popc(m3 & lm);
        sval[rr][0] = s0 ? ssc[min(r0, SELK)] : 0.f;
        sval[rr][1] = s1 ? ssc[min(r1, SELK)] : 0.f;
        sval[rr][2] = s2 ? ssc[min(r2, SELK)] : 0.f;
        sval[rr][3] = s3 ? ssc[min(r3, SELK)] : 0.f;
    }

    // --- S = A . V^T (vectorized over b), masked softmax -> weights ---
    const float s0c   = ssc[0];
    const float inv96 = 0.1020620726159657f;  // 1/sqrt(96)
    {
        float dot[4][4];
        #pragma unroll
        for (int rr = 0; rr < 4; rr++)
            #pragma unroll
            for (int c = 0; c < 4; c++) dot[rr][c] = 0.f;

        const float4* vp0 = (const float4*)(Vr + (lane     )*VRS);
        const float4* vp1 = (const float4*)(Vr + (lane + 32)*VRS);
        const float4* vp2 = (const float4*)(Vr + (lane + 64)*VRS);
        const float4* vp3 = (const float4*)(Vr + (lane + 96)*VRS);
        const float4* ap0 = (const float4*)(As + (4*w + 0)*DD);
        const float4* ap1 = (const float4*)(As + (4*w + 1)*DD);
        const float4* ap2 = (const float4*)(As + (4*w + 2)*DD);
        const float4* ap3 = (const float4*)(As + (4*w + 3)*DD);
        #pragma unroll 2
        for (int b4 = 0; b4 < DD/4; b4++) {
            float4 v0 = vp0[b4], v1 = vp1[b4], v2 = vp2[b4], v3 = vp3[b4];
            float4 av0 = ap0[b4], av1 = ap1[b4], av2 = ap2[b4], av3 = ap3[b4];
            dot[0][0] += av0.x*v0.x + av0.y*v0.y + av0.z*v0.z + av0.w*v0.w;
            dot[0][1] += av0.x*v1.x + av0.y*v1.y + av0.z*v1.z + av0.w*v1.w;
            dot[0][2] += av0.x*v2.x + av0.y*v2.y + av0.z*v2.z + av0.w*v2.w;
            dot[0][3] += av0.x*v3.x + av0.y*v3.y + av0.z*v3.z + av0.w*v3.w;
            dot[1][0] += av1.x*v0.x + av1.y*v0.y + av1.z*v0.z + av1.w*v0.w;
            dot[1][1] += av1.x*v1.x + av1.y*v1.y + av1.z*v1.z + av1.w*v1.w;
            dot[1][2] += av1.x*v2.x + av1.y*v2.y + av1.z*v2.z + av1.w*v2.w;
            dot[1][3] += av1.x*v3.x + av1.y*v3.y + av1.z*v3.z + av1.w*v3.w;
            dot[2][0] += av2.x*v0.x + av2.y*v0.y + av2.z*v0.z + av2.w*v0.w;
            dot[2][1] += av2.x*v1.x + av2.y*v1.y + av2.z*v1.z + av2.w*v1.w;
            dot[2][2] += av2.x*v2.x + av2.y*v2.y + av2.z*v2.z + av2.w*v2.w;
            dot[2][3] += av2.x*v3.x + av2.y*v3.y + av2.z*v3.z + av2.w*v3.w;
            dot[3][0] += av3.x*v0.x + av3.y*v0.y + av3.z*v0.z + av3.w*v0.w;
            dot[3][1] += av3.x*v1.x + av3.y*v1.y + av3.z*v1.z + av3.w*v1.w;
            dot[3][2] += av3.x*v2.x + av3.y*v2.y + av3.z*v2.z + av3.w*v2.w;
            dot[3][3] += av3.x*v3.x + av3.y*v3.y + av3.z*v3.z + av3.w*v3.w;
        }

        float cv[4];
        #pragma unroll
        for (int c = 0; c < 4; c++) cv[c] = cvs[lane + 32*c];

        #pragma unroll
        for (int rr = 0; rr < 4; rr++) {
            float sc[4];
            float mx = -1e30f;
            #pragma unroll
            for (int c = 0; c < 4; c++) {
                float s = sval[rr][c] * (s0c * dot[rr][c] + cv[c]) * inv96;
                sc[c] = (sval[rr][c] != 0.f) ? s : -1e30f;
                mx = fmaxf(mx, sc[c]);
            }
            #pragma unroll
            for (int o = 16; o > 0; o >>= 1)
                mx = fmaxf(mx, __shfl_xor_sync(FULL, mx, o));
            float e[4], sum = 0.f;
            #pragma unroll
            for (int c = 0; c < 4; c++) { e[c] = __expf(sc[c] - mx); sum += e[c]; }
            #pragma unroll
            for (int o = 16; o > 0; o >>= 1)
                sum += __shfl_xor_sync(FULL, sum, o);
            float rs = 1.0f / sum;
            #pragma unroll
            for (int c = 0; c < 4; c++)
                sval[rr][c] = sval[rr][c] * e[c] * rs;   // final combined weight
        }
    }

    // --- Os = Wfull (32x128) @ V (128x96); weights broadcast via shfl ---
    float o0[4], o1[4], o2[4];
    #pragma unroll
    for (int rr = 0; rr < 4; rr++) { o0[rr]=0.f; o1[rr]=0.f; o2[rr]=0.f; }
    {
        const float* vb0 = Vr + lane;
        const float* vb1 = Vr + lane + 32;
        const float* vb2 = Vr + lane + 64;
        #pragma unroll 1
        for (int c4 = 0; c4 < 4; c4++) {
            #pragma unroll 4
            for (int l = 0; l < 32; l++) {
                int i = c4*32 + l;
                float v0 = vb0[i*VRS];
                float v1 = vb1[i*VRS];
                float v2 = vb2[i*VRS];
                #pragma unroll
                for (int rr = 0; rr < 4; rr++) {
                    float wv = __shfl_sync(FULL, sval[rr][c4], l);
                    o0[rr] += wv*v0; o1[rr] += wv*v1; o2[rr] += wv*v2;
                }
            }
        }
    }
    __syncwarp();   // all lanes finished reading As (dot phase) before overwrite
    #pragma unroll
    for (int rr = 0; rr < 4; rr++) {
        As[(4*w+rr)*DD + lane]      = o0[rr];
        As[(4*w+rr)*DD + lane + 32] = o1[rr];
        As[(4*w+rr)*DD + lane + 64] = o2[rr];
    }
    __syncwarp();

    // --- final = Os @ W_o^T + b_o (vectorized over t, packed Wo), write out ---
    {
        float f0[4], f1[4], f2[4];
        #pragma unroll
        for (int rr = 0; rr < 4; rr++) { f0[rr]=0.f; f1[rr]=0.f; f2[rr]=0.f; }
        const float4* os0 = (const float4*)(As + (4*w + 0)*DD);
        const float4* os1 = (const float4*)(As + (4*w + 1)*DD);
        const float4* os2 = (const float4*)(As + (4*w + 2)*DD);
        const float4* os3 = (const float4*)(As + (4*w + 3)*DD);
        #pragma unroll 4
        for (int t4 = 0; t4 < DD/4; t4++) {
            float4 w0 = g_Wp[t4*DD + lane];
            float4 w1 = g_Wp[t4*DD + lane + 32];
            float4 w2 = g_Wp[t4*DD + lane + 64];
            float4 q0 = os0[t4], q1 = os1[t4], q2 = os2[t4], q3 = os3[t4];
            f0[0] += q0.x*w0.x + q0.y*w0.y + q0.z*w0.z + q0.w*w0.w;
            f1[0] += q0.x*w1.x + q0.y*w1.y + q0.z*w1.z + q0.w*w1.w;
            f2[0] += q0.x*w2.x + q0.y*w2.y + q0.z*w2.z + q0.w*w2.w;
            f0[1] += q1.x*w0.x + q1.y*w0.y + q1.z*w0.z + q1.w*w0.w;
            f1[1] += q1.x*w1.x + q1.y*w1.y + q1.z*w1.z + q1.w*w1.w;
            f2[1] += q1.x*w2.x + q1.y*w2.y + q1.z*w2.z + q1.w*w2.w;
            f0[2] += q2.x*w0.x + q2.y*w0.y + q2.z*w0.z + q2.w*w0.w;
            f1[2] += q2.x*w1.x + q2.y*w1.y + q2.z*w1.z + q2.w*w1.w;
            f2[2] += q2.x*w2.x + q2.y*w2.y + q2.z*w2.z + q2.w*w2.w;
            f0[3] += q3.x*w0.x + q3.y*w0.y + q3.z*w0.z + q3.w*w0.w;
            f1[3] += q3.x*w1.x + q3.y*w1.y + q3.z*w1.z + q3.w*w1.w;
            f2[3] += q3.x*w2.x + q3.y*w2.y + q3.z*w2.z + q3.w*w2.w;
        }
        float bb0 = b_o[lane], bb1 = b_o[lane+32], bb2 = b_o[lane+64];
        #pragma unroll
        for (int rr = 0; rr < 4; rr++) {
            int arow = row_base + 4*w + rr;
            float* op = out + (size_t)tile*P*DD + (size_t)arow*DD;
            op[lane]      = f0[rr] + bb0;
            op[lane + 32] = f1[rr] + bb1;
            op[lane + 64] = f2[rr] + bb2;
        }
    }
}

extern "C" void kernel_launch(void* const* d_in, const int* in_sizes, int n_in,
                              void* d_out, int out_size)
{
    const float* attn = (const float*)d_in[0];
    const float* v    = (const float*)d_in[1];
    const float* mb   = (const float*)d_in[2];
    // d_in[3]=w_sub, d_in[4]=b_sub : dead code (softmax over size-1 axis)
    const float* w_up = (const float*)d_in[5];
    const float* b_up = (const float*)d_in[6];
    const float* w_q  = (const float*)d_in[7];
    const float* b_q  = (const float*)d_in[8];
    const float* w_k  = (const float*)d_in[9];
    // d_in[10]=b_k : row-constant in scores, cancels in softmax
    const float* w_o  = (const float*)d_in[11];
    const float* b_o  = (const float*)d_in[12];

    const size_t SMEM = (size_t)(P*VRS + RPC*DD + P + 104) * sizeof(float);
    cudaFuncSetAttribute(fused_kernel, cudaFuncAttributeMaxDynamicSharedMemorySize, (int)SMEM);

    setup_kernel<<<DD/2 + 1, 128>>>(mb, w_up, b_up, w_q, b_q, w_k, w_o);
    fused_kernel<<<TILES * SPLIT, NT, SMEM>>>(attn, v, b_o, (float*)d_out);
}

// round 15
// speedup vs baseline: 1.6318x; 1.0841x over previous
#include <cuda_runtime.h>
#include <stdint.h>
#include <math.h>

#define NT 256

static const int TILES = 64;   // N*W = 4*16
static const int P     = 128;
static const int DD    = 96;
static const int SELK  = 100;
static const int GCHN  = 101;
static const int LCHN  = 80;
static const int SPLIT = 4;
static const int RPC   = 32;   // rows per CTA (4 per warp)
static const int VRS   = 100;  // V row stride (floats); 400B rows -> 16B aligned

typedef unsigned long long u64;

// packed f32x2 FMA: d = a*b + d (two independent fp32 lanes, full precision)
__device__ __forceinline__ void ffma2(u64& d, u64 a, u64 b) {
    asm("fma.rn.f32x2 %0, %1, %2, %0;" : "+l"(d) : "l"(a), "l"(b));
}
__device__ __forceinline__ float hsum2(u64 p) {
    float lo, hi;
    asm("mov.b64 {%0, %1}, %2;" : "=f"(lo), "=f"(hi) : "l"(p));
    return lo + hi;
}

// k-block-major packed weights: coalesced 16B loads, k-pairs adjacent for f32x2
__device__ __align__(16) float4 g_Mp[(DD/4)*DD];  // [b4][j] = M[4b4..4b4+3][j]
__device__ __align__(16) float4 g_Wp[(DD/4)*DD];  // [t4][d] = w_o[d][4t4..4t4+3]
__device__ __align__(16) float g_c[DD];           // W_k^T b_q
__device__ float g_scale[GCHN];                   // sigmoid(mb @ w_up^T + b_up)

__global__ void setup_kernel(const float* __restrict__ mb,
                             const float* __restrict__ w_up,
                             const float* __restrict__ b_up,
                             const float* __restrict__ w_q,
                             const float* __restrict__ b_q,
                             const float* __restrict__ w_k,
                             const float* __restrict__ w_o)
{
    int blk = blockIdx.x;
    int t   = threadIdx.x;
    if (blk < DD/4) {
        if (t < DD) {
            float a0=0.f, a1=0.f, a2=0.f, a3=0.f;
            int b = blk*4;
            #pragma unroll 8
            for (int k = 0; k < DD; k++) {
                float wk = w_k[k*DD + t];
                a0 += w_q[k*DD + b+0] * wk;
                a1 += w_q[k*DD + b+1] * wk;
                a2 += w_q[k*DD + b+2] * wk;
                a3 += w_q[k*DD + b+3] * wk;
            }
            g_Mp[blk*DD + t] = make_float4(a0, a1, a2, a3);
        }
    } else if (blk < DD/2) {
        int t4 = blk - DD/4;
        if (t < DD) {
            const float* wr = w_o + t*DD + t4*4;
            g_Wp[t4*DD + t] = make_float4(wr[0], wr[1], wr[2], wr[3]);
        }
    } else {
        if (t < DD) {
            float acc = 0.f;
            #pragma unroll 8
            for (int k = 0; k < DD; k++)
                acc += b_q[k] * w_k[k*DD + t];
            g_c[t] = acc;
        }
        if (t < GCHN) {
            float acc = b_up[t];
            #pragma unroll 8
            for (int l = 0; l < LCHN; l++)
                acc += w_up[t*LCHN + l] * mb[l];
            g_scale[t] = 1.f / (1.f + __expf(-acc));
        }
    }
}

__global__ __launch_bounds__(NT, 2) void fused_kernel(
    const float* __restrict__ attn,
    const float* __restrict__ v,
    const float* __restrict__ b_o,
    float* __restrict__ out)
{
    extern __shared__ float sm[];
    float* Vr  = sm;              // [P][VRS]  V row-major
    float* As  = Vr + P*VRS;      // [RPC][DD] A = V_rows @ M ; later reused as Os
    float* cvs = As + RPC*DD;     // [P]       c . V_i
    float* ssc = cvs + P;         // [104]     scale table

    const int tile = blockIdx.x / SPLIT;
    const int part = blockIdx.x % SPLIT;
    const int tid  = threadIdx.x;
    const int w    = tid >> 5;
    const int lane = tid & 31;
    const int row_base = part * RPC;
    const unsigned FULL = 0xffffffffu;

    // --- load V tile row-major, float4 end to end ---
    const float4* vt4 = (const float4*)(v + (size_t)tile * P * DD);
    #pragma unroll
    for (int k = 0; k < (P*DD/4)/NT; k++) {     // 12 iterations
        int f = tid + k*NT;
        int i = f / 24;
        int d4 = f - i*24;
        *(float4*)(Vr + i*VRS + d4*4) = vt4[f];
    }
    if (tid < GCHN) ssc[tid] = g_scale[tid];
    __syncthreads();

    // --- cvs[i] = sum_b c[b] * V[i][b] (packed) ---
    if (tid < P) {
        const ulonglong2* vp = (const ulonglong2*)(Vr + tid*VRS);
        const ulonglong2* cp = (const ulonglong2*)g_c;
        u64 acc = 0ull;
        #pragma unroll 6
        for (int b4 = 0; b4 < DD/4; b4++) {
            ulonglong2 vv = vp[b4];
            ulonglong2 cc = cp[b4];
            ffma2(acc, vv.x, cc.x);
            ffma2(acc, vv.y, cc.y);
        }
        cvs[tid] = hsum2(acc);
    }
    __syncthreads();

    // --- attn rows straight to registers as ordered uints (early LDG) ---
    const float* at = attn + (size_t)tile * P * P;
    uint32_t u[4][4];
    #pragma unroll
    for (int rr = 0; rr < 4; rr++) {
        const float* arow = at + (size_t)(row_base + 4*w + rr) * P;
        #pragma unroll
        for (int c = 0; c < 4; c++) {
            uint32_t s = __float_as_uint(arow[lane + 32*c]);
            u[rr][c] = s ^ ((uint32_t)((int32_t)s >> 31) | 0x80000000u);
        }
    }

    // --- Phase A: As[r][j] = sum_b V[row][b] * M[b][j], packed f32x2 ---
    {
        u64 ap[4][3];
        #pragma unroll
        for (int rr = 0; rr < 4; rr++)
            #pragma unroll
            for (int cg = 0; cg < 3; cg++) ap[rr][cg] = 0ull;
        const ulonglong2* vp0 = (const ulonglong2*)(Vr + (row_base + 4*w + 0)*VRS);
        const ulonglong2* vp1 = (const ulonglong2*)(Vr + (row_base + 4*w + 1)*VRS);
        const ulonglong2* vp2 = (const ulonglong2*)(Vr + (row_base + 4*w + 2)*VRS);
        const ulonglong2* vp3 = (const ulonglong2*)(Vr + (row_base + 4*w + 3)*VRS);
        const ulonglong2* mp  = (const ulonglong2*)g_Mp;
        #pragma unroll 4
        for (int b4 = 0; b4 < DD/4; b4++) {
            ulonglong2 vv0 = vp0[b4], vv1 = vp1[b4], vv2 = vp2[b4], vv3 = vp3[b4];
            #pragma unroll
            for (int cg = 0; cg < 3; cg++) {
                ulonglong2 m = mp[b4*DD + lane + 32*cg];
                ffma2(ap[0][cg], vv0.x, m.x); ffma2(ap[0][cg], vv0.y, m.y);
                ffma2(ap[1][cg], vv1.x, m.x); ffma2(ap[1][cg], vv1.y, m.y);
                ffma2(ap[2][cg], vv2.x, m.x); ffma2(ap[2][cg], vv2.y, m.y);
                ffma2(ap[3][cg], vv3.x, m.x); ffma2(ap[3][cg], vv3.y, m.y);
            }
        }
        #pragma unroll
        for (int rr = 0; rr < 4; rr++) {
            As[(4*w+rr)*DD + lane]      = hsum2(ap[rr][0]);
            As[(4*w+rr)*DD + lane + 32] = hsum2(ap[rr][1]);
            As[(4*w+rr)*DD + lane + 64] = hsum2(ap[rr][2]);
        }
    }
    __syncwarp();

    // --- Top-100 per row via radix bisection on ordered-uint prefixes ---
    uint32_t pre[4] = {0u, 0u, 0u, 0u};
    #pragma unroll 1
    for (int bb = 31; bb >= 0; bb--) {
        uint32_t bit = 1u << bb;
        #pragma unroll
        for (int rr = 0; rr < 4; rr++) {
            uint32_t cand = pre[rr] | bit;
            int lc = (int)(u[rr][0] >= cand) + (int)(u[rr][1] >= cand)
                   + (int)(u[rr][2] >= cand) + (int)(u[rr][3] >= cand);
            int tot = __reduce_add_sync(FULL, lc);
            if (tot >= SELK) pre[rr] = cand;
        }
    }

    // --- selected mask + ascending-index rank -> scale value (registers) ---
    float sval[4][4];
    #pragma unroll
    for (int rr = 0; rr < 4; rr++) {
        bool s0 = u[rr][0] >= pre[rr];
        bool s1 = u[rr][1] >= pre[rr];
        bool s2 = u[rr][2] >= pre[rr];
        bool s3 = u[rr][3] >= pre[rr];
        unsigned m0 = __ballot_sync(FULL, s0);
        unsigned m1 = __ballot_sync(FULL, s1);
        unsigned m2 = __ballot_sync(FULL, s2);
        unsigned m3 = __ballot_sync(FULL, s3);
        unsigned lm = (1u << lane) - 1u;
        int t0 = __popc(m0), t1 = __popc(m1), t2 = __popc(m2);
        int r0 = 1 + __popc(m0 & lm);
        int r1 = 1 + t0 + __popc(m1 & lm);
        int r2 = 1 + t0 + t1 + __popc(m2 & lm);
        int r3 = 1 + t0 + t1 + t2 + __popc(m3 & lm);
        sval[rr][0] = s0 ? ssc[min(r0, SELK)] : 0.f;
        sval[rr][1] = s1 ? ssc[min(r1, SELK)] : 0.f;
        sval[rr][2] = s2 ? ssc[min(r2, SELK)] : 0.f;
        sval[rr][3] = s3 ? ssc[min(r3, SELK)] : 0.f;
    }

    // --- S = A . V^T (packed f32x2), masked softmax -> weights ---
    const float s0c   = ssc[0];
    const float inv96 = 0.1020620726159657f;  // 1/sqrt(96)
    {
        u64 dp[4][4];
        #pragma unroll
        for (int rr = 0; rr < 4; rr++)
            #pragma unroll
            for (int c = 0; c < 4; c++) dp[rr][c] = 0ull;

        const ulonglong2* vq0 = (const ulonglong2*)(Vr + (lane     )*VRS);
        const ulonglong2* vq1 = (const ulonglong2*)(Vr + (lane + 32)*VRS);
        const ulonglong2* vq2 = (const ulonglong2*)(Vr + (lane + 64)*VRS);
        const ulonglong2* vq3 = (const ulonglong2*)(Vr + (lane + 96)*VRS);
        const ulonglong2* aq0 = (const ulonglong2*)(As + (4*w + 0)*DD);
        const ulonglong2* aq1 = (const ulonglong2*)(As + (4*w + 1)*DD);
        const ulonglong2* aq2 = (const ulonglong2*)(As + (4*w + 2)*DD);
        const ulonglong2* aq3 = (const ulonglong2*)(As + (4*w + 3)*DD);
        #pragma unroll 2
        for (int b4 = 0; b4 < DD/4; b4++) {
            ulonglong2 av0 = aq0[b4], av1 = aq1[b4], av2 = aq2[b4], av3 = aq3[b4];
            {
                ulonglong2 vv = vq0[b4];
                ffma2(dp[0][0], av0.x, vv.x); ffma2(dp[0][0], av0.y, vv.y);
                ffma2(dp[1][0], av1.x, vv.x); ffma2(dp[1][0], av1.y, vv.y);
                ffma2(dp[2][0], av2.x, vv.x); ffma2(dp[2][0], av2.y, vv.y);
                ffma2(dp[3][0], av3.x, vv.x); ffma2(dp[3][0], av3.y, vv.y);
            }
            {
                ulonglong2 vv = vq1[b4];
                ffma2(dp[0][1], av0.x, vv.x); ffma2(dp[0][1], av0.y, vv.y);
                ffma2(dp[1][1], av1.x, vv.x); ffma2(dp[1][1], av1.y, vv.y);
                ffma2(dp[2][1], av2.x, vv.x); ffma2(dp[2][1], av2.y, vv.y);
                ffma2(dp[3][1], av3.x, vv.x); ffma2(dp[3][1], av3.y, vv.y);
            }
            {
                ulonglong2 vv = vq2[b4];
                ffma2(dp[0][2], av0.x, vv.x); ffma2(dp[0][2], av0.y, vv.y);
                ffma2(dp[1][2], av1.x, vv.x); ffma2(dp[1][2], av1.y, vv.y);
                ffma2(dp[2][2], av2.x, vv.x); ffma2(dp[2][2], av2.y, vv.y);
                ffma2(dp[3][2], av3.x, vv.x); ffma2(dp[3][2], av3.y, vv.y);
            }
            {
                ulonglong2 vv = vq3[b4];
                ffma2(dp[0][3], av0.x, vv.x); ffma2(dp[0][3], av0.y, vv.y);
                ffma2(dp[1][3], av1.x, vv.x); ffma2(dp[1][3], av1.y, vv.y);
                ffma2(dp[2][3], av2.x, vv.x); ffma2(dp[2][3], av2.y, vv.y);
                ffma2(dp[3][3], av3.x, vv.x); ffma2(dp[3][3], av3.y, vv.y);
            }
        }

        float cv[4];
        #pragma unroll
        for (int c = 0; c < 4; c++) cv[c] = cvs[lane + 32*c];

        #pragma unroll
        for (int rr = 0; rr < 4; rr++) {
            float sc[4];
            float mx = -1e30f;
            #pragma unroll
            for (int c = 0; c < 4; c++) {
                float d = hsum2(dp[rr][c]);
                float s = sval[rr][c] * (s0c * d + cv[c]) * inv96;
                sc[c] = (sval[rr][c] != 0.f) ? s : -1e30f;
                mx = fmaxf(mx, sc[c]);
            }
            #pragma unroll
            for (int o = 16; o > 0; o >>= 1)
                mx = fmaxf(mx, __shfl_xor_sync(FULL, mx, o));
            float e[4], sum = 0.f;
            #pragma unroll
            for (int c = 0; c < 4; c++) { e[c] = __expf(sc[c] - mx); sum += e[c]; }
            #pragma unroll
            for (int o = 16; o > 0; o >>= 1)
                sum += __shfl_xor_sync(FULL, sum, o);
            float rs = 1.0f / sum;
            #pragma unroll
            for (int c = 0; c < 4; c++)
                sval[rr][c] = sval[rr][c] * e[c] * rs;   // final combined weight
        }
    }

    // --- Os = Wfull (32x128) @ V (128x96); weights broadcast via shfl ---
    float o0[4], o1[4], o2[4];
    #pragma unroll
    for (int rr = 0; rr < 4; rr++) { o0[rr]=0.f; o1[rr]=0.f; o2[rr]=0.f; }
    {
        const float* vb0 = Vr + lane;
        const float* vb1 = Vr + lane + 32;
        const float* vb2 = Vr + lane + 64;
        #pragma unroll 1
        for (int c4 = 0; c4 < 4; c4++) {
            #pragma unroll 4
            for (int l = 0; l < 32; l++) {
                int i = c4*32 + l;
                float v0 = vb0[i*VRS];
                float v1 = vb1[i*VRS];
                float v2 = vb2[i*VRS];
                #pragma unroll
                for (int rr = 0; rr < 4; rr++) {
                    float wv = __shfl_sync(FULL, sval[rr][c4], l);
                    o0[rr] += wv*v0; o1[rr] += wv*v1; o2[rr] += wv*v2;
                }
            }
        }
    }
    __syncwarp();   // all lanes finished reading As (dot phase) before overwrite
    #pragma unroll
    for (int rr = 0; rr < 4; rr++) {
        As[(4*w+rr)*DD + lane]      = o0[rr];
        As[(4*w+rr)*DD + lane + 32] = o1[rr];
        As[(4*w+rr)*DD + lane + 64] = o2[rr];
    }
    __syncwarp();

    // --- final = Os @ W_o^T + b_o, packed f32x2, write out ---
    {
        u64 fp_[4][3];
        #pragma unroll
        for (int rr = 0; rr < 4; rr++)
            #pragma unroll
            for (int cg = 0; cg < 3; cg++) fp_[rr][cg] = 0ull;
        const ulonglong2* os0 = (const ulonglong2*)(As + (4*w + 0)*DD);
        const ulonglong2* os1 = (const ulonglong2*)(As + (4*w + 1)*DD);
        const ulonglong2* os2 = (const ulonglong2*)(As + (4*w + 2)*DD);
        const ulonglong2* os3 = (const ulonglong2*)(As + (4*w + 3)*DD);
        const ulonglong2* wp  = (const ulonglong2*)g_Wp;
        #pragma unroll 4
        for (int t4 = 0; t4 < DD/4; t4++) {
            ulonglong2 q0 = os0[t4], q1 = os1[t4], q2 = os2[t4], q3 = os3[t4];
            #pragma unroll
            for (int cg = 0; cg < 3; cg++) {
                ulonglong2 ww = wp[t4*DD + lane + 32*cg];
                ffma2(fp_[0][cg], q0.x, ww.x); ffma2(fp_[0][cg], q0.y, ww.y);
                ffma2(fp_[1][cg], q1.x, ww.x); ffma2(fp_[1][cg], q1.y, ww.y);
                ffma2(fp_[2][cg], q2.x, ww.x); ffma2(fp_[2][cg], q2.y, ww.y);
                ffma2(fp_[3][cg], q3.x, ww.x); ffma2(fp_[3][cg], q3.y, ww.y);
            }
        }
        float bb0 = b_o[lane], bb1 = b_o[lane+32], bb2 = b_o[lane+64];
        #pragma unroll
        for (int rr = 0; rr < 4; rr++) {
            int arow = row_base + 4*w + rr;
            float* op = out + (size_t)tile*P*DD + (size_t)arow*DD;
            op[lane]      = hsum2(fp_[rr][0]) + bb0;
            op[lane + 32] = hsum2(fp_[rr][1]) + bb1;
            op[lane + 64] = hsum2(fp_[rr][2]) + bb2;
        }
    }
}

extern "C" void kernel_launch(void* const* d_in, const int* in_sizes, int n_in,
                              void* d_out, int out_size)
{
    const float* attn = (const float*)d_in[0];
    const float* v    = (const float*)d_in[1];
    const float* mb   = (const float*)d_in[2];
    // d_in[3]=w_sub, d_in[4]=b_sub : dead code (softmax over size-1 axis)
    const float* w_up = (const float*)d_in[5];
    const float* b_up = (const float*)d_in[6];
    const float* w_q  = (const float*)d_in[7];
    const float* b_q  = (const float*)d_in[8];
    const float* w_k  = (const float*)d_in[9];
    // d_in[10]=b_k : row-constant in scores, cancels in softmax
    const float* w_o  = (const float*)d_in[11];
    const float* b_o  = (const float*)d_in[12];

    const size_t SMEM = (size_t)(P*VRS + RPC*DD + P + 104) * sizeof(float);
    cudaFuncSetAttribute(fused_kernel, cudaFuncAttributeMaxDynamicSharedMemorySize, (int)SMEM);

    setup_kernel<<<DD/2 + 1, 128>>>(mb, w_up, b_up, w_q, b_q, w_k, w_o);
    fused_kernel<<<TILES * SPLIT, NT, SMEM>>>(attn, v, b_o, (float*)d_out);
}

// round 16
// speedup vs baseline: 2.0428x; 1.2519x over previous
#include <cuda_runtime.h>
#include <stdint.h>
#include <math.h>

#define NT 256

static const int TILES = 64;   // N*W = 4*16
static const int P     = 128;
static const int DD    = 96;
static const int SELK  = 100;
static const int GCHN  = 101;
static const int LCHN  = 80;
static const int SPLIT = 4;
static const int RPC   = 32;   // rows per CTA (4 per warp)
static const int VRS   = 100;  // V row stride (floats); 400B rows, 16B aligned
static const int VTS2  = 66;   // Vt half row stride (even -> LDS.64 clean)

// smem float offsets
static const int SP1OFF = 12800;             // A matrix (stride 96) then Vt halves (stride 66)
static const int SP2OFF = SP1OFF + 6400;     // Ws weights [32][128] then Os-stage rows
static const int CVSOFF = SP2OFF + 4096;
static const int SSCOFF = CVSOFF + 128;
static const int SMTOT  = SSCOFF + 104;      // 23528 floats = 94112 B

typedef unsigned long long u64;

__device__ __forceinline__ void ffma2(u64& d, u64 a, u64 b) {
    asm("fma.rn.f32x2 %0, %1, %2, %0;" : "+l"(d) : "l"(a), "l"(b));
}
__device__ __forceinline__ float hsum2(u64 p) {
    float lo, hi;
    asm("mov.b64 {%0, %1}, %2;" : "=f"(lo), "=f"(hi) : "l"(p));
    return lo + hi;
}

__device__ __align__(16) float4 g_Mp[(DD/4)*DD];  // [b4][j] = M[4b4..4b4+3][j]
__device__ __align__(16) float4 g_Wp[(DD/4)*DD];  // [t4][d] = w_o[d][4t4..4t4+3]
__device__ __align__(16) float g_c[DD];           // W_k^T b_q
__device__ float g_scale[GCHN];                   // sigmoid(mb @ w_up^T + b_up)

__global__ void setup_kernel(const float* __restrict__ mb,
                             const float* __restrict__ w_up,
                             const float* __restrict__ b_up,
                             const float* __restrict__ w_q,
                             const float* __restrict__ b_q,
                             const float* __restrict__ w_k,
                             const float* __restrict__ w_o)
{
    int blk = blockIdx.x;
    int t   = threadIdx.x;
    if (blk < DD/4) {
        if (t < DD) {
            float a0=0.f, a1=0.f, a2=0.f, a3=0.f;
            int b = blk*4;
            #pragma unroll 8
            for (int k = 0; k < DD; k++) {
                float wk = w_k[k*DD + t];
                a0 += w_q[k*DD + b+0] * wk;
                a1 += w_q[k*DD + b+1] * wk;
                a2 += w_q[k*DD + b+2] * wk;
                a3 += w_q[k*DD + b+3] * wk;
            }
            g_Mp[blk*DD + t] = make_float4(a0, a1, a2, a3);
        }
    } else if (blk < DD/2) {
        int t4 = blk - DD/4;
        if (t < DD) {
            const float* wr = w_o + t*DD + t4*4;
            g_Wp[t4*DD + t] = make_float4(wr[0], wr[1], wr[2], wr[3]);
        }
    } else {
        if (t < DD) {
            float acc = 0.f;
            #pragma unroll 8
            for (int k = 0; k < DD; k++)
                acc += b_q[k] * w_k[k*DD + t];
            g_c[t] = acc;
        }
        if (t < GCHN) {
            float acc = b_up[t];
            #pragma unroll 8
            for (int l = 0; l < LCHN; l++)
                acc += w_up[t*LCHN + l] * mb[l];
            g_scale[t] = 1.f / (1.f + __expf(-acc));
        }
    }
}

__global__ __launch_bounds__(NT, 2) void fused_kernel(
    const float* __restrict__ attn,
    const float* __restrict__ v,
    const float* __restrict__ b_o,
    float* __restrict__ out)
{
    extern __shared__ float sm[];
    float* Vr  = sm;              // [P][VRS]
    float* As  = sm + SP1OFF;     // A matrix, stride DD
    float* Vt  = sm + SP1OFF;     // later: V^T half, stride VTS2
    float* Ws  = sm + SP2OFF;     // weights [RPC][128]; later Os-stage rows (stride 128)
    float* cvs = sm + CVSOFF;
    float* ssc = sm + SSCOFF;

    const int tile = blockIdx.x / SPLIT;
    const int part = blockIdx.x % SPLIT;
    const int tid  = threadIdx.x;
    const int w    = tid >> 5;
    const int lane = tid & 31;
    const int row_base = part * RPC;
    const unsigned FULL = 0xffffffffu;

    // --- load V tile row-major, float4 end to end ---
    const float4* vt4 = (const float4*)(v + (size_t)tile * P * DD);
    #pragma unroll
    for (int k = 0; k < (P*DD/4)/NT; k++) {     // 12 iterations
        int f = tid + k*NT;
        int i = f / 24;
        int d4 = f - i*24;
        *(float4*)(Vr + i*VRS + d4*4) = vt4[f];
    }
    if (tid < GCHN) ssc[tid] = g_scale[tid];
    __syncthreads();

    // --- cvs[i] = sum_b c[b] * V[i][b] (packed) ---
    if (tid < P) {
        const ulonglong2* vp = (const ulonglong2*)(Vr + tid*VRS);
        const ulonglong2* cp = (const ulonglong2*)g_c;
        u64 acc = 0ull;
        #pragma unroll 6
        for (int b4 = 0; b4 < DD/4; b4++) {
            ulonglong2 vv = vp[b4];
            ulonglong2 cc = cp[b4];
            ffma2(acc, vv.x, cc.x);
            ffma2(acc, vv.y, cc.y);
        }
        cvs[tid] = hsum2(acc);
    }
    __syncthreads();

    // --- attn rows straight to registers as ordered uints (early LDG) ---
    const float* at = attn + (size_t)tile * P * P;
    uint32_t u[4][4];
    #pragma unroll
    for (int rr = 0; rr < 4; rr++) {
        const float* arow = at + (size_t)(row_base + 4*w + rr) * P;
        #pragma unroll
        for (int c = 0; c < 4; c++) {
            uint32_t s = __float_as_uint(arow[lane + 32*c]);
            u[rr][c] = s ^ ((uint32_t)((int32_t)s >> 31) | 0x80000000u);
        }
    }

    // --- Phase A: As[r][j] = sum_b V[row][b] * M[b][j], packed f32x2 ---
    {
        u64 ap[4][3];
        #pragma unroll
        for (int rr = 0; rr < 4; rr++)
            #pragma unroll
            for (int cg = 0; cg < 3; cg++) ap[rr][cg] = 0ull;
        const ulonglong2* vp0 = (const ulonglong2*)(Vr + (row_base + 4*w + 0)*VRS);
        const ulonglong2* vp1 = (const ulonglong2*)(Vr + (row_base + 4*w + 1)*VRS);
        const ulonglong2* vp2 = (const ulonglong2*)(Vr + (row_base + 4*w + 2)*VRS);
        const ulonglong2* vp3 = (const ulonglong2*)(Vr + (row_base + 4*w + 3)*VRS);
        const ulonglong2* mp  = (const ulonglong2*)g_Mp;
        #pragma unroll 4
        for (int b4 = 0; b4 < DD/4; b4++) {
            ulonglong2 vv0 = vp0[b4], vv1 = vp1[b4], vv2 = vp2[b4], vv3 = vp3[b4];
            #pragma unroll
            for (int cg = 0; cg < 3; cg++) {
                ulonglong2 m = mp[b4*DD + lane + 32*cg];
                ffma2(ap[0][cg], vv0.x, m.x); ffma2(ap[0][cg], vv0.y, m.y);
                ffma2(ap[1][cg], vv1.x, m.x); ffma2(ap[1][cg], vv1.y, m.y);
                ffma2(ap[2][cg], vv2.x, m.x); ffma2(ap[2][cg], vv2.y, m.y);
                ffma2(ap[3][cg], vv3.x, m.x); ffma2(ap[3][cg], vv3.y, m.y);
            }
        }
        #pragma unroll
        for (int rr = 0; rr < 4; rr++) {
            As[(4*w+rr)*DD + lane]      = hsum2(ap[rr][0]);
            As[(4*w+rr)*DD + lane + 32] = hsum2(ap[rr][1]);
            As[(4*w+rr)*DD + lane + 64] = hsum2(ap[rr][2]);
        }
    }
    __syncwarp();

    // --- Top-100 per row: byte-packed radix bisection, exact early exit ---
    // invariant: count(u >= pre[rr]) >= SELK. When count == SELK exactly, the
    // top-100 set is fully determined -> row done.
    uint32_t pre[4] = {0u, 0u, 0u, 0u};
    {
        unsigned doneMask = 0u;
        for (int bb = 31; bb >= 0 && doneMask != 0xFu; bb--) {
            uint32_t bit = 1u << bb;
            uint32_t packed = 0u;
            #pragma unroll
            for (int rr = 0; rr < 4; rr++) {
                uint32_t cand = pre[rr] | bit;
                uint32_t lc = (uint32_t)(u[rr][0] >= cand) + (uint32_t)(u[rr][1] >= cand)
                            + (uint32_t)(u[rr][2] >= cand) + (uint32_t)(u[rr][3] >= cand);
                packed += lc << (8*rr);
            }
            uint32_t tot = __reduce_add_sync(FULL, packed);  // per-byte sums (<=128, no carry)
            #pragma unroll
            for (int rr = 0; rr < 4; rr++) {
                if (!((doneMask >> rr) & 1u)) {
                    int t = (int)((tot >> (8*rr)) & 0xffu);
                    if (t >= SELK) {
                        pre[rr] |= bit;
                        if (t == SELK) doneMask |= 1u << rr;
                    }
                }
            }
        }
    }

    // --- selected mask + ascending-index rank -> scale value (registers) ---
    float sval[4][4];
    #pragma unroll
    for (int rr = 0; rr < 4; rr++) {
        bool s0 = u[rr][0] >= pre[rr];
        bool s1 = u[rr][1] >= pre[rr];
        bool s2 = u[rr][2] >= pre[rr];
        bool s3 = u[rr][3] >= pre[rr];
        unsigned m0 = __ballot_sync(FULL, s0);
        unsigned m1 = __ballot_sync(FULL, s1);
        unsigned m2 = __ballot_sync(FULL, s2);
        unsigned m3 = __ballot_sync(FULL, s3);
        unsigned lm = (1u << lane) - 1u;
        int t0 = __popc(m0), t1 = __popc(m1), t2 = __popc(m2);
        int r0 = 1 + __popc(m0 & lm);
        int r1 = 1 + t0 + __popc(m1 & lm);
        int r2 = 1 + t0 + t1 + __popc(m2 & lm);
        int r3 = 1 + t0 + t1 + t2 + __popc(m3 & lm);
        sval[rr][0] = s0 ? ssc[min(r0, SELK)] : 0.f;
        sval[rr][1] = s1 ? ssc[min(r1, SELK)] : 0.f;
        sval[rr][2] = s2 ? ssc[min(r2, SELK)] : 0.f;
        sval[rr][3] = s3 ? ssc[min(r3, SELK)] : 0.f;
    }

    // --- S = A . V^T (packed f32x2), masked softmax -> weights ---
    const float s0c   = ssc[0];
    const float inv96 = 0.1020620726159657f;  // 1/sqrt(96)
    {
        u64 dp[4][4];
        #pragma unroll
        for (int rr = 0; rr < 4; rr++)
            #pragma unroll
            for (int c = 0; c < 4; c++) dp[rr][c] = 0ull;

        const ulonglong2* vq0 = (const ulonglong2*)(Vr + (lane     )*VRS);
        const ulonglong2* vq1 = (const ulonglong2*)(Vr + (lane + 32)*VRS);
        const ulonglong2* vq2 = (const ulonglong2*)(Vr + (lane + 64)*VRS);
        const ulonglong2* vq3 = (const ulonglong2*)(Vr + (lane + 96)*VRS);
        const ulonglong2* aq0 = (const ulonglong2*)(As + (4*w + 0)*DD);
        const ulonglong2* aq1 = (const ulonglong2*)(As + (4*w + 1)*DD);
        const ulonglong2* aq2 = (const ulonglong2*)(As + (4*w + 2)*DD);
        const ulonglong2* aq3 = (const ulonglong2*)(As + (4*w + 3)*DD);
        #pragma unroll 2
        for (int b4 = 0; b4 < DD/4; b4++) {
            ulonglong2 av0 = aq0[b4], av1 = aq1[b4], av2 = aq2[b4], av3 = aq3[b4];
            {
                ulonglong2 vv = vq0[b4];
                ffma2(dp[0][0], av0.x, vv.x); ffma2(dp[0][0], av0.y, vv.y);
                ffma2(dp[1][0], av1.x, vv.x); ffma2(dp[1][0], av1.y, vv.y);
                ffma2(dp[2][0], av2.x, vv.x); ffma2(dp[2][0], av2.y, vv.y);
                ffma2(dp[3][0], av3.x, vv.x); ffma2(dp[3][0], av3.y, vv.y);
            }
            {
                ulonglong2 vv = vq1[b4];
                ffma2(dp[0][1], av0.x, vv.x); ffma2(dp[0][1], av0.y, vv.y);
                ffma2(dp[1][1], av1.x, vv.x); ffma2(dp[1][1], av1.y, vv.y);
                ffma2(dp[2][1], av2.x, vv.x); ffma2(dp[2][1], av2.y, vv.y);
                ffma2(dp[3][1], av3.x, vv.x); ffma2(dp[3][1], av3.y, vv.y);
            }
            {
                ulonglong2 vv = vq2[b4];
                ffma2(dp[0][2], av0.x, vv.x); ffma2(dp[0][2], av0.y, vv.y);
                ffma2(dp[1][2], av1.x, vv.x); ffma2(dp[1][2], av1.y, vv.y);
                ffma2(dp[2][2], av2.x, vv.x); ffma2(dp[2][2], av2.y, vv.y);
                ffma2(dp[3][2], av3.x, vv.x); ffma2(dp[3][2], av3.y, vv.y);
            }
            {
                ulonglong2 vv = vq3[b4];
                ffma2(dp[0][3], av0.x, vv.x); ffma2(dp[0][3], av0.y, vv.y);
                ffma2(dp[1][3], av1.x, vv.x); ffma2(dp[1][3], av1.y, vv.y);
                ffma2(dp[2][3], av2.x, vv.x); ffma2(dp[2][3], av2.y, vv.y);
                ffma2(dp[3][3], av3.x, vv.x); ffma2(dp[3][3], av3.y, vv.y);
            }
        }

        float cv[4];
        #pragma unroll
        for (int c = 0; c < 4; c++) cv[c] = cvs[lane + 32*c];

        #pragma unroll
        for (int rr = 0; rr < 4; rr++) {
            float sc[4];
            float mx = -1e30f;
            #pragma unroll
            for (int c = 0; c < 4; c++) {
                float d = hsum2(dp[rr][c]);
                float s = sval[rr][c] * (s0c * d + cv[c]) * inv96;
                sc[c] = (sval[rr][c] != 0.f) ? s : -1e30f;
                mx = fmaxf(mx, sc[c]);
            }
            #pragma unroll
            for (int o = 16; o > 0; o >>= 1)
                mx = fmaxf(mx, __shfl_xor_sync(FULL, mx, o));
            float e[4], sum = 0.f;
            #pragma unroll
            for (int c = 0; c < 4; c++) { e[c] = __expf(sc[c] - mx); sum += e[c]; }
            #pragma unroll
            for (int o = 16; o > 0; o >>= 1)
                sum += __shfl_xor_sync(FULL, sum, o);
            float rs = 1.0f / sum;
            #pragma unroll
            for (int c = 0; c < 4; c++)
                sval[rr][c] = sval[rr][c] * e[c] * rs;   // final combined weight
        }
    }

    // --- stage weights into Ws[row][i] (own-warp rows) ---
    #pragma unroll
    for (int rr = 0; rr < 4; rr++)
        #pragma unroll
        for (int c4 = 0; c4 < 4; c4++)
            Ws[(4*w+rr)*128 + c4*32 + lane] = sval[rr][c4];

    // all warps must finish reading A (dot) before Vt overwrites SP1;
    // all Ws writes visible before Os reads (own-warp anyway)
    __syncthreads();

    // --- Os = Wfull @ V via i-packed f32x2, V transposed half-by-half ---
    u64 ac[4][3];
    #pragma unroll
    for (int rr = 0; rr < 4; rr++)
        #pragma unroll
        for (int cg = 0; cg < 3; cg++) ac[rr][cg] = 0ull;

    #pragma unroll 1
    for (int h = 0; h < 2; h++) {
        // transpose V half h: Vt[d][il] = V[h*64+il][d]
        #pragma unroll
        for (int k = 0; k < 6; k++) {
            int f  = tid + k*NT;        // 0..1535
            int il = f / 24;            // 0..63
            int d4 = f - il*24;         // 0..23
            float4 val = *(const float4*)(Vr + (h*64 + il)*VRS + d4*4);
            Vt[(4*d4+0)*VTS2 + il] = val.x;
            Vt[(4*d4+1)*VTS2 + il] = val.y;
            Vt[(4*d4+2)*VTS2 + il] = val.z;
            Vt[(4*d4+3)*VTS2 + il] = val.w;
        }
        __syncthreads();

        const u64* wr0 = (const u64*)(Ws + (4*w+0)*128 + h*64);
        const u64* wr1 = (const u64*)(Ws + (4*w+1)*128 + h*64);
        const u64* wr2 = (const u64*)(Ws + (4*w+2)*128 + h*64);
        const u64* wr3 = (const u64*)(Ws + (4*w+3)*128 + h*64);
        const u64* vt0 = (const u64*)(Vt + (lane     )*VTS2);
        const u64* vt1 = (const u64*)(Vt + (lane + 32)*VTS2);
        const u64* vt2 = (const u64*)(Vt + (lane + 64)*VTS2);
        #pragma unroll 4
        for (int p = 0; p < 32; p++) {
            u64 v0 = vt0[p], v1 = vt1[p], v2 = vt2[p];
            u64 w0 = wr0[p], w1 = wr1[p], w2 = wr2[p], w3 = wr3[p];
            ffma2(ac[0][0], w0, v0); ffma2(ac[0][1], w0, v1); ffma2(ac[0][2], w0, v2);
            ffma2(ac[1][0], w1, v0); ffma2(ac[1][1], w1, v1); ffma2(ac[1][2], w1, v2);
            ffma2(ac[2][0], w2, v0); ffma2(ac[2][1], w2, v1); ffma2(ac[2][2], w2, v2);
            ffma2(ac[3][0], w3, v0); ffma2(ac[3][1], w3, v1); ffma2(ac[3][2], w3, v2);
        }
        __syncthreads();   // half h consumed by all warps before next transpose
    }

    // --- stage Os rows into SP2 (overwrites own-warp Ws rows, stride 128) ---
    #pragma unroll
    for (int rr = 0; rr < 4; rr++) {
        Ws[(4*w+rr)*128 + lane]      = hsum2(ac[rr][0]);
        Ws[(4*w+rr)*128 + lane + 32] = hsum2(ac[rr][1]);
        Ws[(4*w+rr)*128 + lane + 64] = hsum2(ac[rr][2]);
    }
    __syncwarp();

    // --- final = Os @ W_o^T + b_o, packed f32x2, write out ---
    {
        u64 fp_[4][3];
        #pragma unroll
        for (int rr = 0; rr < 4; rr++)
            #pragma unroll
            for (int cg = 0; cg < 3; cg++) fp_[rr][cg] = 0ull;
        const ulonglong2* os0 = (const ulonglong2*)(Ws + (4*w + 0)*128);
        const ulonglong2* os1 = (const ulonglong2*)(Ws + (4*w + 1)*128);
        const ulonglong2* os2 = (const ulonglong2*)(Ws + (4*w + 2)*128);
        const ulonglong2* os3 = (const ulonglong2*)(Ws + (4*w + 3)*128);
        const ulonglong2* wp  = (const ulonglong2*)g_Wp;
        #pragma unroll 4
        for (int t4 = 0; t4 < DD/4; t4++) {
            ulonglong2 q0 = os0[t4], q1 = os1[t4], q2 = os2[t4], q3 = os3[t4];
            #pragma unroll
            for (int cg = 0; cg < 3; cg++) {
                ulonglong2 ww = wp[t4*DD + lane + 32*cg];
                ffma2(fp_[0][cg], q0.x, ww.x); ffma2(fp_[0][cg], q0.y, ww.y);
                ffma2(fp_[1][cg], q1.x, ww.x); ffma2(fp_[1][cg], q1.y, ww.y);
                ffma2(fp_[2][cg], q2.x, ww.x); ffma2(fp_[2][cg], q2.y, ww.y);
                ffma2(fp_[3][cg], q3.x, ww.x); ffma2(fp_[3][cg], q3.y, ww.y);
            }
        }
        float bb0 = b_o[lane], bb1 = b_o[lane+32], bb2 = b_o[lane+64];
        #pragma unroll
        for (int rr = 0; rr < 4; rr++) {
            int arow = row_base + 4*w + rr;
            float* op = out + (size_t)tile*P*DD + (size_t)arow*DD;
            op[lane]      = hsum2(fp_[rr][0]) + bb0;
            op[lane + 32] = hsum2(fp_[rr][1]) + bb1;
            op[lane + 64] = hsum2(fp_[rr][2]) + bb2;
        }
    }
}

extern "C" void kernel_launch(void* const* d_in, const int* in_sizes, int n_in,
                              void* d_out, int out_size)
{
    const float* attn = (const float*)d_in[0];
    const float* v    = (const float*)d_in[1];
    const float* mb   = (const float*)d_in[2];
    // d_in[3]=w_sub, d_in[4]=b_sub : dead code (softmax over size-1 axis)
    const float* w_up = (const float*)d_in[5];
    const float* b_up = (const float*)d_in[6];
    const float* w_q  = (const float*)d_in[7];
    const float* b_q  = (const float*)d_in[8];
    const float* w_k  = (const float*)d_in[9];
    // d_in[10]=b_k : row-constant in scores, cancels in softmax
    const float* w_o  = (const float*)d_in[11];
    const float* b_o  = (const float*)d_in[12];

    const size_t SMEM = (size_t)SMTOT * sizeof(float);
    cudaFuncSetAttribute(fused_kernel, cudaFuncAttributeMaxDynamicSharedMemorySize, (int)SMEM);

    setup_kernel<<<DD/2 + 1, 128>>>(mb, w_up, b_up, w_q, b_q, w_k, w_o);
    fused_kernel<<<TILES * SPLIT, NT, SMEM>>>(attn, v, b_o, (float*)d_out);
}

// round 17
// speedup vs baseline: 2.1116x; 1.0337x over previous
#include <cuda_runtime.h>
#include <stdint.h>
#include <math.h>

#define NT 256

static const int TILES = 64;   // N*W = 4*16
static const int P     = 128;
static const int DD    = 96;
static const int SELK  = 100;
static const int GCHN  = 101;
static const int LCHN  = 80;
static const int SPLIT = 4;
static const int RPC   = 32;   // rows per CTA (4 per warp)
static const int VRS   = 100;  // V row stride (floats); 400B rows, 16B aligned
static const int VTS2  = 68;   // Vt half row stride: 272B rows -> 16B aligned, conflict-free

// smem float offsets
static const int SP1OFF = 12800;             // A matrix (stride 96) then Vt halves (stride 68)
static const int SP2OFF = SP1OFF + 6528;     // Ws weights [32][128] then Os-stage rows
static const int CVSOFF = SP2OFF + 4096;
static const int SSCOFF = CVSOFF + 128;
static const int SMTOT  = SSCOFF + 104;      // 23656 floats = 94624 B

typedef unsigned long long u64;

__device__ __forceinline__ void ffma2(u64& d, u64 a, u64 b) {
    asm("fma.rn.f32x2 %0, %1, %2, %0;" : "+l"(d) : "l"(a), "l"(b));
}
__device__ __forceinline__ float hsum2(u64 p) {
    float lo, hi;
    asm("mov.b64 {%0, %1}, %2;" : "=f"(lo), "=f"(hi) : "l"(p));
    return lo + hi;
}

__device__ __align__(16) float4 g_Mp[(DD/4)*DD];  // [b4][j] = M[4b4..4b4+3][j]
__device__ __align__(16) float4 g_Wp[(DD/4)*DD];  // [t4][d] = w_o[d][4t4..4t4+3]
__device__ __align__(16) float g_c[DD];           // W_k^T b_q
__device__ float g_scale[GCHN];                   // sigmoid(mb @ w_up^T + b_up)

__global__ void setup_kernel(const float* __restrict__ mb,
                             const float* __restrict__ w_up,
                             const float* __restrict__ b_up,
                             const float* __restrict__ w_q,
                             const float* __restrict__ b_q,
                             const float* __restrict__ w_k,
                             const float* __restrict__ w_o)
{
    int blk = blockIdx.x;
    int t   = threadIdx.x;
    if (blk < DD/4) {
        if (t < DD) {
            float a0=0.f, a1=0.f, a2=0.f, a3=0.f;
            int b = blk*4;
            #pragma unroll 8
            for (int k = 0; k < DD; k++) {
                float wk = w_k[k*DD + t];
                a0 += w_q[k*DD + b+0] * wk;
                a1 += w_q[k*DD + b+1] * wk;
                a2 += w_q[k*DD + b+2] * wk;
                a3 += w_q[k*DD + b+3] * wk;
            }
            g_Mp[blk*DD + t] = make_float4(a0, a1, a2, a3);
        }
    } else if (blk < DD/2) {
        int t4 = blk - DD/4;
        if (t < DD) {
            const float* wr = w_o + t*DD + t4*4;
            g_Wp[t4*DD + t] = make_float4(wr[0], wr[1], wr[2], wr[3]);
        }
    } else {
        if (t < DD) {
            float acc = 0.f;
            #pragma unroll 8
            for (int k = 0; k < DD; k++)
                acc += b_q[k] * w_k[k*DD + t];
            g_c[t] = acc;
        }
        if (t < GCHN) {
            float acc = b_up[t];
            #pragma unroll 8
            for (int l = 0; l < LCHN; l++)
                acc += w_up[t*LCHN + l] * mb[l];
            g_scale[t] = 1.f / (1.f + __expf(-acc));
        }
    }
}

__global__ __launch_bounds__(NT, 2) void fused_kernel(
    const float* __restrict__ attn,
    const float* __restrict__ v,
    const float* __restrict__ b_o,
    float* __restrict__ out)
{
    extern __shared__ float sm[];
    float* Vr  = sm;              // [P][VRS]
    float* As  = sm + SP1OFF;     // A matrix, stride DD
    float* Vt  = sm + SP1OFF;     // later: V^T half, stride VTS2
    float* Ws  = sm + SP2OFF;     // weights [RPC][128]; later Os-stage rows (stride 128)
    float* cvs = sm + CVSOFF;
    float* ssc = sm + SSCOFF;

    const int tile = blockIdx.x / SPLIT;
    const int part = blockIdx.x % SPLIT;
    const int tid  = threadIdx.x;
    const int w    = tid >> 5;
    const int lane = tid & 31;
    const int row_base = part * RPC;
    const unsigned FULL = 0xffffffffu;

    // --- load V tile row-major, float4 end to end ---
    const float4* vt4 = (const float4*)(v + (size_t)tile * P * DD);
    #pragma unroll
    for (int k = 0; k < (P*DD/4)/NT; k++) {     // 12 iterations
        int f = tid + k*NT;
        int i = f / 24;
        int d4 = f - i*24;
        *(float4*)(Vr + i*VRS + d4*4) = vt4[f];
    }
    if (tid < GCHN) ssc[tid] = g_scale[tid];
    __syncthreads();

    // --- cvs[i] = sum_b c[b] * V[i][b] (packed) ---
    if (tid < P) {
        const ulonglong2* vp = (const ulonglong2*)(Vr + tid*VRS);
        const ulonglong2* cp = (const ulonglong2*)g_c;
        u64 acc = 0ull;
        #pragma unroll 6
        for (int b4 = 0; b4 < DD/4; b4++) {
            ulonglong2 vv = vp[b4];
            ulonglong2 cc = cp[b4];
            ffma2(acc, vv.x, cc.x);
            ffma2(acc, vv.y, cc.y);
        }
        cvs[tid] = hsum2(acc);
    }
    __syncthreads();

    // --- attn rows straight to registers as ordered uints (early LDG) ---
    const float* at = attn + (size_t)tile * P * P;
    uint32_t u[4][4];
    #pragma unroll
    for (int rr = 0; rr < 4; rr++) {
        const float* arow = at + (size_t)(row_base + 4*w + rr) * P;
        #pragma unroll
        for (int c = 0; c < 4; c++) {
            uint32_t s = __float_as_uint(arow[lane + 32*c]);
            u[rr][c] = s ^ ((uint32_t)((int32_t)s >> 31) | 0x80000000u);
        }
    }

    // --- Phase A: As[r][j] = sum_b V[row][b] * M[b][j], packed f32x2 ---
    {
        u64 ap[4][3];
        #pragma unroll
        for (int rr = 0; rr < 4; rr++)
            #pragma unroll
            for (int cg = 0; cg < 3; cg++) ap[rr][cg] = 0ull;
        const ulonglong2* vp0 = (const ulonglong2*)(Vr + (row_base + 4*w + 0)*VRS);
        const ulonglong2* vp1 = (const ulonglong2*)(Vr + (row_base + 4*w + 1)*VRS);
        const ulonglong2* vp2 = (const ulonglong2*)(Vr + (row_base + 4*w + 2)*VRS);
        const ulonglong2* vp3 = (const ulonglong2*)(Vr + (row_base + 4*w + 3)*VRS);
        const ulonglong2* mp  = (const ulonglong2*)g_Mp;
        #pragma unroll 4
        for (int b4 = 0; b4 < DD/4; b4++) {
            ulonglong2 vv0 = vp0[b4], vv1 = vp1[b4], vv2 = vp2[b4], vv3 = vp3[b4];
            #pragma unroll
            for (int cg = 0; cg < 3; cg++) {
                ulonglong2 m = mp[b4*DD + lane + 32*cg];
                ffma2(ap[0][cg], vv0.x, m.x); ffma2(ap[0][cg], vv0.y, m.y);
                ffma2(ap[1][cg], vv1.x, m.x); ffma2(ap[1][cg], vv1.y, m.y);
                ffma2(ap[2][cg], vv2.x, m.x); ffma2(ap[2][cg], vv2.y, m.y);
                ffma2(ap[3][cg], vv3.x, m.x); ffma2(ap[3][cg], vv3.y, m.y);
            }
        }
        #pragma unroll
        for (int rr = 0; rr < 4; rr++) {
            As[(4*w+rr)*DD + lane]      = hsum2(ap[rr][0]);
            As[(4*w+rr)*DD + lane + 32] = hsum2(ap[rr][1]);
            As[(4*w+rr)*DD + lane + 64] = hsum2(ap[rr][2]);
        }
    }
    __syncwarp();

    // --- Top-100 per row: byte-packed radix bisection, exact early exit ---
    uint32_t pre[4] = {0u, 0u, 0u, 0u};
    {
        unsigned doneMask = 0u;
        for (int bb = 31; bb >= 0 && doneMask != 0xFu; bb--) {
            uint32_t bit = 1u << bb;
            uint32_t packed = 0u;
            #pragma unroll
            for (int rr = 0; rr < 4; rr++) {
                uint32_t cand = pre[rr] | bit;
                uint32_t lc = (uint32_t)(u[rr][0] >= cand) + (uint32_t)(u[rr][1] >= cand)
                            + (uint32_t)(u[rr][2] >= cand) + (uint32_t)(u[rr][3] >= cand);
                packed += lc << (8*rr);
            }
            uint32_t tot = __reduce_add_sync(FULL, packed);  // per-byte sums (<=128, no carry)
            #pragma unroll
            for (int rr = 0; rr < 4; rr++) {
                if (!((doneMask >> rr) & 1u)) {
                    int t = (int)((tot >> (8*rr)) & 0xffu);
                    if (t >= SELK) {
                        pre[rr] |= bit;
                        if (t == SELK) doneMask |= 1u << rr;
                    }
                }
            }
        }
    }

    // --- selected mask + ascending-index rank -> scale value (registers) ---
    float sval[4][4];
    #pragma unroll
    for (int rr = 0; rr < 4; rr++) {
        bool s0 = u[rr][0] >= pre[rr];
        bool s1 = u[rr][1] >= pre[rr];
        bool s2 = u[rr][2] >= pre[rr];
        bool s3 = u[rr][3] >= pre[rr];
        unsigned m0 = __ballot_sync(FULL, s0);
        unsigned m1 = __ballot_sync(FULL, s1);
        unsigned m2 = __ballot_sync(FULL, s2);
        unsigned m3 = __ballot_sync(FULL, s3);
        unsigned lm = (1u << lane) - 1u;
        int t0 = __popc(m0), t1 = __popc(m1), t2 = __popc(m2);
        int r0 = 1 + __popc(m0 & lm);
        int r1 = 1 + t0 + __popc(m1 & lm);
        int r2 = 1 + t0 + t1 + __popc(m2 & lm);
        int r3 = 1 + t0 + t1 + t2 + __popc(m3 & lm);
        sval[rr][0] = s0 ? ssc[min(r0, SELK)] : 0.f;
        sval[rr][1] = s1 ? ssc[min(r1, SELK)] : 0.f;
        sval[rr][2] = s2 ? ssc[min(r2, SELK)] : 0.f;
        sval[rr][3] = s3 ? ssc[min(r3, SELK)] : 0.f;
    }

    // --- S = A . V^T (packed f32x2), masked softmax -> weights ---
    const float s0c   = ssc[0];
    const float inv96 = 0.1020620726159657f;  // 1/sqrt(96)
    {
        u64 dp[4][4];
        #pragma unroll
        for (int rr = 0; rr < 4; rr++)
            #pragma unroll
            for (int c = 0; c < 4; c++) dp[rr][c] = 0ull;

        const ulonglong2* vq0 = (const ulonglong2*)(Vr + (lane     )*VRS);
        const ulonglong2* vq1 = (const ulonglong2*)(Vr + (lane + 32)*VRS);
        const ulonglong2* vq2 = (const ulonglong2*)(Vr + (lane + 64)*VRS);
        const ulonglong2* vq3 = (const ulonglong2*)(Vr + (lane + 96)*VRS);
        const ulonglong2* aq0 = (const ulonglong2*)(As + (4*w + 0)*DD);
        const ulonglong2* aq1 = (const ulonglong2*)(As + (4*w + 1)*DD);
        const ulonglong2* aq2 = (const ulonglong2*)(As + (4*w + 2)*DD);
        const ulonglong2* aq3 = (const ulonglong2*)(As + (4*w + 3)*DD);
        #pragma unroll 2
        for (int b4 = 0; b4 < DD/4; b4++) {
            ulonglong2 av0 = aq0[b4], av1 = aq1[b4], av2 = aq2[b4], av3 = aq3[b4];
            {
                ulonglong2 vv = vq0[b4];
                ffma2(dp[0][0], av0.x, vv.x); ffma2(dp[0][0], av0.y, vv.y);
                ffma2(dp[1][0], av1.x, vv.x); ffma2(dp[1][0], av1.y, vv.y);
                ffma2(dp[2][0], av2.x, vv.x); ffma2(dp[2][0], av2.y, vv.y);
                ffma2(dp[3][0], av3.x, vv.x); ffma2(dp[3][0], av3.y, vv.y);
            }
            {
                ulonglong2 vv = vq1[b4];
                ffma2(dp[0][1], av0.x, vv.x); ffma2(dp[0][1], av0.y, vv.y);
                ffma2(dp[1][1], av1.x, vv.x); ffma2(dp[1][1], av1.y, vv.y);
                ffma2(dp[2][1], av2.x, vv.x); ffma2(dp[2][1], av2.y, vv.y);
                ffma2(dp[3][1], av3.x, vv.x); ffma2(dp[3][1], av3.y, vv.y);
            }
            {
                ulonglong2 vv = vq2[b4];
                ffma2(dp[0][2], av0.x, vv.x); ffma2(dp[0][2], av0.y, vv.y);
                ffma2(dp[1][2], av1.x, vv.x); ffma2(dp[1][2], av1.y, vv.y);
                ffma2(dp[2][2], av2.x, vv.x); ffma2(dp[2][2], av2.y, vv.y);
                ffma2(dp[3][2], av3.x, vv.x); ffma2(dp[3][2], av3.y, vv.y);
            }
            {
                ulonglong2 vv = vq3[b4];
                ffma2(dp[0][3], av0.x, vv.x); ffma2(dp[0][3], av0.y, vv.y);
                ffma2(dp[1][3], av1.x, vv.x); ffma2(dp[1][3], av1.y, vv.y);
                ffma2(dp[2][3], av2.x, vv.x); ffma2(dp[2][3], av2.y, vv.y);
                ffma2(dp[3][3], av3.x, vv.x); ffma2(dp[3][3], av3.y, vv.y);
            }
        }

        float cv[4];
        #pragma unroll
        for (int c = 0; c < 4; c++) cv[c] = cvs[lane + 32*c];

        #pragma unroll
        for (int rr = 0; rr < 4; rr++) {
            float sc[4];
            float mx = -1e30f;
            #pragma unroll
            for (int c = 0; c < 4; c++) {
                float d = hsum2(dp[rr][c]);
                float s = sval[rr][c] * (s0c * d + cv[c]) * inv96;
                sc[c] = (sval[rr][c] != 0.f) ? s : -1e30f;
                mx = fmaxf(mx, sc[c]);
            }
            #pragma unroll
            for (int o = 16; o > 0; o >>= 1)
                mx = fmaxf(mx, __shfl_xor_sync(FULL, mx, o));
            float e[4], sum = 0.f;
            #pragma unroll
            for (int c = 0; c < 4; c++) { e[c] = __expf(sc[c] - mx); sum += e[c]; }
            #pragma unroll
            for (int o = 16; o > 0; o >>= 1)
                sum += __shfl_xor_sync(FULL, sum, o);
            float rs = 1.0f / sum;
            #pragma unroll
            for (int c = 0; c < 4; c++)
                sval[rr][c] = sval[rr][c] * e[c] * rs;   // final combined weight
        }
    }

    // --- stage weights into Ws[row][i] (own-warp rows) ---
    #pragma unroll
    for (int rr = 0; rr < 4; rr++)
        #pragma unroll
        for (int c4 = 0; c4 < 4; c4++)
            Ws[(4*w+rr)*128 + c4*32 + lane] = sval[rr][c4];

    __syncthreads();   // A reads done before Vt overwrite; Ws visible

    // --- Os = Wfull @ V via i-packed f32x2, V transposed half-by-half ---
    u64 ac[4][3];
    #pragma unroll
    for (int rr = 0; rr < 4; rr++)
        #pragma unroll
        for (int cg = 0; cg < 3; cg++) ac[rr][cg] = 0ull;

    #pragma unroll 1
    for (int h = 0; h < 2; h++) {
        // transpose V half h: Vt[d][il] = V[h*64+il][d]; lanes vary il -> conflict-free
        #pragma unroll
        for (int k = 0; k < 6; k++) {
            int f  = tid + k*NT;        // 0..1535
            int il = f & 63;
            int d4 = f >> 6;            // 0..23
            float4 val = *(const float4*)(Vr + (h*64 + il)*VRS + d4*4);
            Vt[(4*d4+0)*VTS2 + il] = val.x;
            Vt[(4*d4+1)*VTS2 + il] = val.y;
            Vt[(4*d4+2)*VTS2 + il] = val.z;
            Vt[(4*d4+3)*VTS2 + il] = val.w;
        }
        __syncthreads();

        const ulonglong2* wr0 = (const ulonglong2*)(Ws + (4*w+0)*128 + h*64);
        const ulonglong2* wr1 = (const ulonglong2*)(Ws + (4*w+1)*128 + h*64);
        const ulonglong2* wr2 = (const ulonglong2*)(Ws + (4*w+2)*128 + h*64);
        const ulonglong2* wr3 = (const ulonglong2*)(Ws + (4*w+3)*128 + h*64);
        const ulonglong2* vt0 = (const ulonglong2*)(Vt + (lane     )*VTS2);
        const ulonglong2* vt1 = (const ulonglong2*)(Vt + (lane + 32)*VTS2);
        const ulonglong2* vt2 = (const ulonglong2*)(Vt + (lane + 64)*VTS2);
        #pragma unroll 4
        for (int p2 = 0; p2 < 16; p2++) {
            ulonglong2 v0 = vt0[p2], v1 = vt1[p2], v2 = vt2[p2];
            ulonglong2 w0 = wr0[p2], w1 = wr1[p2], w2 = wr2[p2], w3 = wr3[p2];
            ffma2(ac[0][0], w0.x, v0.x); ffma2(ac[0][0], w0.y, v0.y);
            ffma2(ac[0][1], w0.x, v1.x); ffma2(ac[0][1], w0.y, v1.y);
            ffma2(ac[0][2], w0.x, v2.x); ffma2(ac[0][2], w0.y, v2.y);
            ffma2(ac[1][0], w1.x, v0.x); ffma2(ac[1][0], w1.y, v0.y);
            ffma2(ac[1][1], w1.x, v1.x); ffma2(ac[1][1], w1.y, v1.y);
            ffma2(ac[1][2], w1.x, v2.x); ffma2(ac[1][2], w1.y, v2.y);
            ffma2(ac[2][0], w2.x, v0.x); ffma2(ac[2][0], w2.y, v0.y);
            ffma2(ac[2][1], w2.x, v1.x); ffma2(ac[2][1], w2.y, v1.y);
            ffma2(ac[2][2], w2.x, v2.x); ffma2(ac[2][2], w2.y, v2.y);
            ffma2(ac[3][0], w3.x, v0.x); ffma2(ac[3][0], w3.y, v0.y);
            ffma2(ac[3][1], w3.x, v1.x); ffma2(ac[3][1], w3.y, v1.y);
            ffma2(ac[3][2], w3.x, v2.x); ffma2(ac[3][2], w3.y, v2.y);
        }
        __syncthreads();   // half h consumed before next transpose
    }

    // NOTE: p2 above indexes ulonglong2 (4 floats): 16 iters cover 64 i's per half.

    // --- stage Os rows into SP2 (overwrites own-warp Ws rows, stride 128) ---
    #pragma unroll
    for (int rr = 0; rr < 4; rr++) {
        Ws[(4*w+rr)*128 + lane]      = hsum2(ac[rr][0]);
        Ws[(4*w+rr)*128 + lane + 32] = hsum2(ac[rr][1]);
        Ws[(4*w+rr)*128 + lane + 64] = hsum2(ac[rr][2]);
    }
    __syncwarp();

    // --- final = Os @ W_o^T + b_o, packed f32x2, write out ---
    {
        u64 fp_[4][3];
        #pragma unroll
        for (int rr = 0; rr < 4; rr++)
            #pragma unroll
            for (int cg = 0; cg < 3; cg++) fp_[rr][cg] = 0ull;
        const ulonglong2* os0 = (const ulonglong2*)(Ws + (4*w + 0)*128);
        const ulonglong2* os1 = (const ulonglong2*)(Ws + (4*w + 1)*128);
        const ulonglong2* os2 = (const ulonglong2*)(Ws + (4*w + 2)*128);
        const ulonglong2* os3 = (const ulonglong2*)(Ws + (4*w + 3)*128);
        const ulonglong2* wp  = (const ulonglong2*)g_Wp;
        #pragma unroll 4
        for (int t4 = 0; t4 < DD/4; t4++) {
            ulonglong2 q0 = os0[t4], q1 = os1[t4], q2 = os2[t4], q3 = os3[t4];
            #pragma unroll
            for (int cg = 0; cg < 3; cg++) {
                ulonglong2 ww = wp[t4*DD + lane + 32*cg];
                ffma2(fp_[0][cg], q0.x, ww.x); ffma2(fp_[0][cg], q0.y, ww.y);
                ffma2(fp_[1][cg], q1.x, ww.x); ffma2(fp_[1][cg], q1.y, ww.y);
                ffma2(fp_[2][cg], q2.x, ww.x); ffma2(fp_[2][cg], q2.y, ww.y);
                ffma2(fp_[3][cg], q3.x, ww.x); ffma2(fp_[3][cg], q3.y, ww.y);
            }
        }
        float bb0 = b_o[lane], bb1 = b_o[lane+32], bb2 = b_o[lane+64];
        #pragma unroll
        for (int rr = 0; rr < 4; rr++) {
            int arow = row_base + 4*w + rr;
            float* op = out + (size_t)tile*P*DD + (size_t)arow*DD;
            op[lane]      = hsum2(fp_[rr][0]) + bb0;
            op[lane + 32] = hsum2(fp_[rr][1]) + bb1;
            op[lane + 64] = hsum2(fp_[rr][2]) + bb2;
        }
    }
}

extern "C" void kernel_launch(void* const* d_in, const int* in_sizes, int n_in,
                              void* d_out, int out_size)
{
    const float* attn = (const float*)d_in[0];
    const float* v    = (const float*)d_in[1];
    const float* mb   = (const float*)d_in[2];
    // d_in[3]=w_sub, d_in[4]=b_sub : dead code (softmax over size-1 axis)
    const float* w_up = (const float*)d_in[5];
    const float* b_up = (const float*)d_in[6];
    const float* w_q  = (const float*)d_in[7];
    const float* b_q  = (const float*)d_in[8];
    const float* w_k  = (const float*)d_in[9];
    // d_in[10]=b_k : row-constant in scores, cancels in softmax
    const float* w_o  = (const float*)d_in[11];
    const float* b_o  = (const float*)d_in[12];

    const size_t SMEM = (size_t)SMTOT * sizeof(float);
    cudaFuncSetAttribute(fused_kernel, cudaFuncAttributeMaxDynamicSharedMemorySize, (int)SMEM);

    setup_kernel<<<DD/2 + 1, 128>>>(mb, w_up, b_up, w_q, b_q, w_k, w_o);
    fused_kernel<<<TILES * SPLIT, NT, SMEM>>>(attn, v, b_o, (float*)d_out);
}